// round 14
// baseline (speedup 1.0000x reference)
#include <cuda_runtime.h>
#include <math.h>

#define THRESH 0.1f

typedef unsigned long long u64;

__device__ __forceinline__ u64 pack2(float lo, float hi) {
    u64 r;
    asm("mov.b64 %0, {%1, %2};" : "=l"(r) : "f"(lo), "f"(hi));
    return r;
}
__device__ __forceinline__ void unpack2(u64 v, float& lo, float& hi) {
    asm("mov.b64 {%0, %1}, %2;" : "=f"(lo), "=f"(hi) : "l"(v));
}
__device__ __forceinline__ u64 fma2(u64 a, u64 b, u64 c) {
    u64 d;
    asm("fma.rn.f32x2 %0, %1, %2, %3;" : "=l"(d) : "l"(a), "l"(b), "l"(c));
    return d;
}

// ---------------- scratch (no allocations allowed) ----------------
__device__ float g_bufA[26214400];
__device__ float g_bufB[13107200];
__device__ float g_w0[9 * 2 * 8];    // [k][ci][co]
__device__ float g_w1[9 * 8 * 16];
__device__ float g_w2[9 * 16 * 32];
__device__ float g_w3[9 * 32 * 64];
__device__ float g_wl[11 * 1024];

__global__ void noop_kernel() {}

// ---------------- fused weight norm (all layers, one launch) ----------------
__global__ void wnorm_all(const float* __restrict__ c0v, const float* __restrict__ c0g,
                          const float* __restrict__ c1v, const float* __restrict__ c1g,
                          const float* __restrict__ c2v, const float* __restrict__ c2g,
                          const float* __restrict__ c3v, const float* __restrict__ c3g,
                          const float* __restrict__ lv,  const float* __restrict__ lg,
                          float* __restrict__ w0, float* __restrict__ w1,
                          float* __restrict__ w2, float* __restrict__ w3,
                          float* __restrict__ wl) {
    int r = blockIdx.x;
    const float* v = 0; const float* g = 0; float* w = 0;
    int CIN = 0, COUT = 0, co = 0;
    bool lin = false;
    if (r < 8)        { v = c0v; g = c0g; w = w0; CIN = 2;  COUT = 8;  co = r; }
    else if (r < 24)  { v = c1v; g = c1g; w = w1; CIN = 8;  COUT = 16; co = r - 8; }
    else if (r < 56)  { v = c2v; g = c2g; w = w2; CIN = 16; COUT = 32; co = r - 24; }
    else if (r < 120) { v = c3v; g = c3g; w = w3; CIN = 32; COUT = 64; co = r - 56; }
    else              { lin = true; co = r - 120; }

    __shared__ float snorm;
    if (!lin) {
        const float* vr = v + (size_t)co * CIN * 9;
        if (threadIdx.x == 0) {
            float s = 0.f;
            for (int i = 0; i < CIN * 9; i++) s = __fadd_rn(s, __fmul_rn(vr[i], vr[i]));
            snorm = sqrtf(s);
        }
        __syncthreads();
        float norm = snorm, gg = g[co];
        for (int idx = threadIdx.x; idx < CIN * 9; idx += blockDim.x) {
            int ci = idx / 9, k = idx % 9;
            w[((size_t)k * CIN + ci) * COUT + co] = __fdiv_rn(__fmul_rn(gg, vr[idx]), norm);
        }
    } else {
        const float* vr = lv + (size_t)co * 1024;
        if (threadIdx.x == 0) {
            float s = 0.f;
            for (int i = 0; i < 1024; i++) s = __fadd_rn(s, __fmul_rn(vr[i], vr[i]));
            snorm = sqrtf(s);
        }
        __syncthreads();
        float norm = snorm, gg = lg[co];
        for (int i = threadIdx.x; i < 1024; i += blockDim.x)
            wl[(size_t)co * 1024 + i] = __fdiv_rn(__fmul_rn(gg, vr[i]), norm);
    }
}

// ---------------- layer 0 fully fused: conv(2->8,64x64) + IAF(T=50) + 2x2 pool ----------------
// v4: 16x16 pre-pool tiles -> 512 blocks x 256 threads (4 cout-groups x 64 pixels).
// Precomputed load slots, double-buffered tile, 1 barrier/t, prefetch overlap.
__global__ void __launch_bounds__(256) l0_fused(const float* __restrict__ x,
                                                const float* __restrict__ wt,
                                                float* __restrict__ out) {
    const int PW = 20, CPH = 18 * 20, BUFSZ = 2 * 18 * 20;   // 720
    __shared__ float sw[144];
    __shared__ float sin[2][BUFSZ];

    const int b = blockIdx.x >> 4;
    const int tile = blockIdx.x & 15;
    const int ty0 = (tile >> 2) * 16;
    const int tx0 = (tile & 3) * 16;
    const int tid = threadIdx.x;
    if (tid < 144) sw[tid] = wt[tid];

    const int cg = tid >> 6;                // 0..3 -> couts {2cg, 2cg+1}
    const int ptid = tid & 63;
    const int py = ptid >> 3, px = ptid & 7;
    const int y0 = 2 * py, x0 = 2 * px;
    const int co0 = cg * 2;

    int srcOff[3], dstOff[3];
    bool ldOk[3], ldAct[3];
#pragma unroll
    for (int j = 0; j < 3; j++) {
        int i = tid + j * 256;
        bool act = i < 648;
        int ii = act ? i : 0;
        int c = ii / 324;
        int r = ii - c * 324;
        int yy = r / 18, xx = r - yy * 18;
        int gy = ty0 + yy - 1, gx = tx0 + xx - 1;
        ldAct[j] = act;
        ldOk[j] = act && gy >= 0 && gy < 64 && gx >= 0 && gx < 64;
        srcOff[j] = c * 4096 + gy * 64 + gx;
        dstOff[j] = c * CPH + yy * PW + xx;
    }

    {
        const float* xp = x + ((size_t)(b * 50)) * 2 * 4096;
#pragma unroll
        for (int j = 0; j < 3; j++) {
            if (ldAct[j]) {
                float v = ldOk[j] ? xp[srcOff[j]] : 0.f;
                sin[0][dstOff[j]] = v;
            }
        }
    }

    float m[2][4];
#pragma unroll
    for (int c = 0; c < 2; c++) { m[c][0] = 0.f; m[c][1] = 0.f; m[c][2] = 0.f; m[c][3] = 0.f; }

    const int Y2 = (ty0 >> 1) + py, X2 = (tx0 >> 1) + px;

    int p = 0;
    for (int t = 0; t < 50; t++) {
        __syncthreads();

        const float* sbuf = sin[p];
        float inr[2][4][4];
#pragma unroll
        for (int ci = 0; ci < 2; ci++) {
#pragma unroll
            for (int r = 0; r < 4; r++) {
                const float* rp = sbuf + ci * CPH + (y0 + r) * PW + x0;
                float2 a = *reinterpret_cast<const float2*>(rp);
                float2 bb = *reinterpret_cast<const float2*>(rp + 2);
                inr[ci][r][0] = a.x; inr[ci][r][1] = a.y;
                inr[ci][r][2] = bb.x; inr[ci][r][3] = bb.y;
            }
        }

        if (t < 49) {
            const float* xp = x + ((size_t)(b * 50 + t + 1)) * 2 * 4096;
            float* dbuf = sin[p ^ 1];
#pragma unroll
            for (int j = 0; j < 3; j++) {
                if (ldAct[j]) {
                    float v = ldOk[j] ? xp[srcOff[j]] : 0.f;
                    dbuf[dstOff[j]] = v;
                }
            }
        }

        float acc[2][4];
#pragma unroll
        for (int c = 0; c < 2; c++) { acc[c][0] = 0.f; acc[c][1] = 0.f; acc[c][2] = 0.f; acc[c][3] = 0.f; }
#pragma unroll
        for (int ky = 0; ky < 3; ky++) {
#pragma unroll
            for (int kx = 0; kx < 3; kx++) {
#pragma unroll
                for (int ci = 0; ci < 2; ci++) {
                    float i00 = inr[ci][ky][kx];
                    float i01 = inr[ci][ky][kx + 1];
                    float i10 = inr[ci][ky + 1][kx];
                    float i11 = inr[ci][ky + 1][kx + 1];
                    const float2 wv = *reinterpret_cast<const float2*>(
                        sw + ((ky * 3 + kx) * 2 + ci) * 8 + co0);
                    acc[0][0] = __fmaf_rn(i00, wv.x, acc[0][0]);
                    acc[0][1] = __fmaf_rn(i01, wv.x, acc[0][1]);
                    acc[0][2] = __fmaf_rn(i10, wv.x, acc[0][2]);
                    acc[0][3] = __fmaf_rn(i11, wv.x, acc[0][3]);
                    acc[1][0] = __fmaf_rn(i00, wv.y, acc[1][0]);
                    acc[1][1] = __fmaf_rn(i01, wv.y, acc[1][1]);
                    acc[1][2] = __fmaf_rn(i10, wv.y, acc[1][2]);
                    acc[1][3] = __fmaf_rn(i11, wv.y, acc[1][3]);
                }
            }
        }

        float* op = out + ((size_t)(b * 50 + t) * 8 + co0) * 1024 + Y2 * 32 + X2;
#pragma unroll
        for (int c = 0; c < 2; c++) {
            float s = 0.f;
            m[c][0] = __fadd_rn(m[c][0], acc[c][0]);
            m[c][1] = __fadd_rn(m[c][1], acc[c][1]);
            m[c][2] = __fadd_rn(m[c][2], acc[c][2]);
            m[c][3] = __fadd_rn(m[c][3], acc[c][3]);
            if (m[c][0] >= THRESH) { m[c][0] = __fadd_rn(m[c][0], -THRESH); s += 0.25f; }
            if (m[c][1] >= THRESH) { m[c][1] = __fadd_rn(m[c][1], -THRESH); s += 0.25f; }
            if (m[c][2] >= THRESH) { m[c][2] = __fadd_rn(m[c][2], -THRESH); s += 0.25f; }
            if (m[c][3] >= THRESH) { m[c][3] = __fadd_rn(m[c][3], -THRESH); s += 0.25f; }
            op[c * 1024] = s;
        }
        p ^= 1;
    }
}

// ---------------- 3x3 SAME conv, packed f32x2 FMAs (best-known config) ----------------
template <int CIN, int COUT, int H, int IPB, int COG, int MINB>
__global__ void __launch_bounds__(256, MINB)
conv3x3_blk(const float* __restrict__ in, const float* __restrict__ wt,
            float* __restrict__ out) {
    const int W = H, HW = H * W, PW = W + 2, PHW = (H + 2) * PW;
    const int HW4 = HW / 4, W2 = W / 2;
    const int CPB = COUT / COG, NCG = CPB / 8;
    extern __shared__ float smem[];
    float* sin = smem;
    float* sw = smem + IPB * CIN * PHW;

    const int ngrp = blockIdx.x / COG;
    const int cog = blockIdx.x - ngrp * COG;
    const int coB = cog * CPB;
    const int n0 = ngrp * IPB;

    for (int i = threadIdx.x; i < IPB * CIN * PHW; i += blockDim.x) sin[i] = 0.f;
    if (COG == 1) {
        for (int i = threadIdx.x; i < 9 * CIN * CPB; i += blockDim.x) sw[i] = wt[i];
    } else {
        for (int i = threadIdx.x; i < 9 * CIN * CPB; i += blockDim.x) {
            int kci = i / CPB, c = i - kci * CPB;
            sw[i] = wt[kci * COUT + coB + c];
        }
    }
    __syncthreads();
    for (int i = threadIdx.x; i < IPB * CIN * HW; i += blockDim.x) {
        int img = i / (CIN * HW);
        int rem = i - img * (CIN * HW);
        int ci = rem / HW;
        int p = rem - ci * HW;
        int y = p / W;
        int x = p - y * W;
        sin[img * CIN * PHW + ci * PHW + (y + 1) * PW + (x + 1)] = in[(size_t)n0 * CIN * HW + i];
    }
    __syncthreads();

    const int ITEMS = IPB * HW4 * NCG;
    for (int item = threadIdx.x; item < ITEMS; item += blockDim.x) {
        int cg = item / (IPB * HW4);
        int rem = item - cg * (IPB * HW4);
        int img = rem / HW4;
        int q = rem - img * HW4;
        int y2 = q / W2, x2 = q - y2 * W2;
        int y0 = 2 * y2, x0 = 2 * x2;
        const float* simg = sin + img * CIN * PHW;

        u64 accP[4][4];
#pragma unroll
        for (int cp = 0; cp < 4; cp++) {
            accP[cp][0] = 0ULL; accP[cp][1] = 0ULL; accP[cp][2] = 0ULL; accP[cp][3] = 0ULL;
        }
#pragma unroll
        for (int ky = 0; ky < 3; ky++) {
#pragma unroll
            for (int kx = 0; kx < 3; kx++) {
                const float* ip = simg + (y0 + ky) * PW + (x0 + kx);
                const float* wp = sw + (ky * 3 + kx) * CIN * CPB + cg * 8;
#pragma unroll 4
                for (int ci = 0; ci < CIN; ci++) {
                    float i00, i01, i10, i11;
                    if (kx != 1) {
                        float2 a = *reinterpret_cast<const float2*>(ip + ci * PHW);
                        float2 bb = *reinterpret_cast<const float2*>(ip + ci * PHW + PW);
                        i00 = a.x; i01 = a.y; i10 = bb.x; i11 = bb.y;
                    } else {
                        i00 = ip[ci * PHW];
                        i01 = ip[ci * PHW + 1];
                        i10 = ip[ci * PHW + PW];
                        i11 = ip[ci * PHW + PW + 1];
                    }
                    u64 p00 = pack2(i00, i00);
                    u64 p01 = pack2(i01, i01);
                    u64 p10 = pack2(i10, i10);
                    u64 p11 = pack2(i11, i11);
                    const ulonglong2* wq2 = reinterpret_cast<const ulonglong2*>(wp + ci * CPB);
                    ulonglong2 wA = wq2[0];
                    ulonglong2 wB = wq2[1];
                    accP[0][0] = fma2(p00, wA.x, accP[0][0]);
                    accP[0][1] = fma2(p01, wA.x, accP[0][1]);
                    accP[0][2] = fma2(p10, wA.x, accP[0][2]);
                    accP[0][3] = fma2(p11, wA.x, accP[0][3]);
                    accP[1][0] = fma2(p00, wA.y, accP[1][0]);
                    accP[1][1] = fma2(p01, wA.y, accP[1][1]);
                    accP[1][2] = fma2(p10, wA.y, accP[1][2]);
                    accP[1][3] = fma2(p11, wA.y, accP[1][3]);
                    accP[2][0] = fma2(p00, wB.x, accP[2][0]);
                    accP[2][1] = fma2(p01, wB.x, accP[2][1]);
                    accP[2][2] = fma2(p10, wB.x, accP[2][2]);
                    accP[2][3] = fma2(p11, wB.x, accP[2][3]);
                    accP[3][0] = fma2(p00, wB.y, accP[3][0]);
                    accP[3][1] = fma2(p01, wB.y, accP[3][1]);
                    accP[3][2] = fma2(p10, wB.y, accP[3][2]);
                    accP[3][3] = fma2(p11, wB.y, accP[3][3]);
                }
            }
        }
        float* op = out + ((size_t)(n0 + img) * COUT + coB + cg * 8) * HW + y0 * W + x0;
#pragma unroll
        for (int cp = 0; cp < 4; cp++) {
            float lo0, hi0, lo1, hi1, lo2, hi2, lo3, hi3;
            unpack2(accP[cp][0], lo0, hi0);
            unpack2(accP[cp][1], lo1, hi1);
            unpack2(accP[cp][2], lo2, hi2);
            unpack2(accP[cp][3], lo3, hi3);
            float* opc = op + (2 * cp) * HW;
            float2 r0; r0.x = lo0; r0.y = lo1;
            float2 r1; r1.x = lo2; r1.y = lo3;
            *reinterpret_cast<float2*>(opc) = r0;
            *reinterpret_cast<float2*>(opc + W) = r1;
            float* opc2 = op + (2 * cp + 1) * HW;
            float2 s0; s0.x = hi0; s0.y = hi1;
            float2 s1; s1.x = hi2; s1.y = hi3;
            *reinterpret_cast<float2*>(opc2) = s0;
            *reinterpret_cast<float2*>(opc2 + W) = s1;
        }
    }
}

// ---------------- fused IAF + 2x2 avg pool: 2 pooled pixels / thread ----------------
template <int C, int H, int T>
__global__ void iaf_pool_kernel(const float* __restrict__ syn, float* __restrict__ out, int B) {
    const int W = H, HW = H * W, H2 = H / 2, W2 = W / 2, HW2 = H2 * W2, WP = W2 / 2;
    int idx = blockIdx.x * blockDim.x + threadIdx.x;
    int total = B * C * H2 * WP;
    if (idx >= total) return;
    int xp = idx % WP;
    int r = idx / WP;
    int y2 = r % H2;
    r /= H2;
    int c = r % C;
    int b = r / C;

    const size_t stride = (size_t)C * HW;
    const size_t ostride = (size_t)C * HW2;
    const float* p = syn + ((size_t)b * T) * stride + (size_t)c * HW + (size_t)(2 * y2) * W + 4 * xp;
    float* q = out + ((size_t)b * T) * ostride + (size_t)c * HW2 + (size_t)y2 * W2 + 2 * xp;

    float v0 = 0.f, v1 = 0.f, v2 = 0.f, v3 = 0.f;
    float u0 = 0.f, u1 = 0.f, u2 = 0.f, u3 = 0.f;
#pragma unroll 2
    for (int t = 0; t < T; t++) {
        const float4 a = *reinterpret_cast<const float4*>(p);
        const float4 bb = *reinterpret_cast<const float4*>(p + W);
        v0 = __fadd_rn(v0, a.x);
        v1 = __fadd_rn(v1, a.y);
        v2 = __fadd_rn(v2, bb.x);
        v3 = __fadd_rn(v3, bb.y);
        u0 = __fadd_rn(u0, a.z);
        u1 = __fadd_rn(u1, a.w);
        u2 = __fadd_rn(u2, bb.z);
        u3 = __fadd_rn(u3, bb.w);
        float s = 0.f, s2 = 0.f;
        if (v0 >= THRESH) { v0 = __fadd_rn(v0, -THRESH); s += 0.25f; }
        if (v1 >= THRESH) { v1 = __fadd_rn(v1, -THRESH); s += 0.25f; }
        if (v2 >= THRESH) { v2 = __fadd_rn(v2, -THRESH); s += 0.25f; }
        if (v3 >= THRESH) { v3 = __fadd_rn(v3, -THRESH); s += 0.25f; }
        if (u0 >= THRESH) { u0 = __fadd_rn(u0, -THRESH); s2 += 0.25f; }
        if (u1 >= THRESH) { u1 = __fadd_rn(u1, -THRESH); s2 += 0.25f; }
        if (u2 >= THRESH) { u2 = __fadd_rn(u2, -THRESH); s2 += 0.25f; }
        if (u3 >= THRESH) { u3 = __fadd_rn(u3, -THRESH); s2 += 0.25f; }
        float2 sv; sv.x = s; sv.y = s2;
        *reinterpret_cast<float2*>(q) = sv;
        p += stride;
        q += ostride;
    }
}

// ---------------- final linear: (BT,1024) @ (11,1024)^T ----------------
__global__ void linear_kernel(const float* __restrict__ in, const float* __restrict__ w,
                              float* __restrict__ out) {
    int n = blockIdx.x;
    __shared__ float srow[1024];
    for (int i = threadIdx.x; i < 1024; i += blockDim.x) srow[i] = in[(size_t)n * 1024 + i];
    __syncthreads();
    int cls = threadIdx.x;
    if (cls >= 11) return;
    const float* wr = w + (size_t)cls * 1024;
    float acc = 0.f;
    for (int i = 0; i < 1024; i++) acc = __fmaf_rn(srow[i], wr[i], acc);
    out[(size_t)n * 11 + cls] = acc;
}

extern "C" void kernel_launch(void* const* d_in, const int* in_sizes, int n_in,
                              void* d_out, int out_size) {
    const float* x   = (const float*)d_in[0];
    const float* c0v = (const float*)d_in[1];
    const float* c0g = (const float*)d_in[2];
    const float* c1v = (const float*)d_in[3];
    const float* c1g = (const float*)d_in[4];
    const float* c2v = (const float*)d_in[5];
    const float* c2g = (const float*)d_in[6];
    const float* c3v = (const float*)d_in[7];
    const float* c3g = (const float*)d_in[8];
    const float* lv  = (const float*)d_in[9];
    const float* lg  = (const float*)d_in[10];

    float *bufA, *bufB, *w0, *w1, *w2, *w3, *wl;
    cudaGetSymbolAddress((void**)&bufA, g_bufA);
    cudaGetSymbolAddress((void**)&bufB, g_bufB);
    cudaGetSymbolAddress((void**)&w0, g_w0);
    cudaGetSymbolAddress((void**)&w1, g_w1);
    cudaGetSymbolAddress((void**)&w2, g_w2);
    cudaGetSymbolAddress((void**)&w3, g_w3);
    cudaGetSymbolAddress((void**)&wl, g_wl);

    const int B = 32, T = 50, BT = B * T;

    // (1) weight norms
    wnorm_all<<<131, 64>>>(c0v, c0g, c1v, c1g, c2v, c2g, c3v, c3g, lv, lg,
                           w0, w1, w2, w3, wl);
    // (2,3) alignment no-ops so l0_fused is the 4th launch (profiled)
    noop_kernel<<<1, 32>>>();
    noop_kernel<<<1, 32>>>();

    const int smem1 = (1 * 8 * 34 * 34 + 9 * 8 * 16) * 4;      // 41600
    const int smem2 = (2 * 16 * 18 * 18 + 9 * 16 * 32) * 4;    // 59904
    const int smem3 = (2 * 32 * 10 * 10 + 9 * 32 * 32) * 4;    // 62464 (COG=2)

    cudaFuncSetAttribute((const void*)conv3x3_blk<8, 16, 32, 1, 1, 4>,
                         cudaFuncAttributeMaxDynamicSharedMemorySize, smem1);
    cudaFuncSetAttribute((const void*)conv3x3_blk<16, 32, 16, 2, 1, 4>,
                         cudaFuncAttributeMaxDynamicSharedMemorySize, smem2);
    cudaFuncSetAttribute((const void*)conv3x3_blk<32, 64, 8, 2, 2, 3>,
                         cudaFuncAttributeMaxDynamicSharedMemorySize, smem3);

    // (4) layer 0 fused — v4 tiling (512 blocks x 256 threads)
    l0_fused<<<B * 16, 256>>>(x, w0, bufB);

    // layer 1
    conv3x3_blk<8, 16, 32, 1, 1, 4><<<BT, 256, smem1>>>(bufB, w1, bufA);
    {
        int total = B * 16 * 16 * 8;
        iaf_pool_kernel<16, 32, 50><<<(total + 255) / 256, 256>>>(bufA, bufB, B);
    }
    // layer 2
    conv3x3_blk<16, 32, 16, 2, 1, 4><<<BT / 2, 256, smem2>>>(bufB, w2, bufA);
    {
        int total = B * 32 * 8 * 4;
        iaf_pool_kernel<32, 16, 50><<<(total + 255) / 256, 256>>>(bufA, bufB, B);
    }
    // layer 3 (COG=2)
    conv3x3_blk<32, 64, 8, 2, 2, 3><<<BT, 256, smem3>>>(bufB, w3, bufA);
    {
        int total = B * 64 * 4 * 2;
        iaf_pool_kernel<64, 8, 50><<<(total + 255) / 256, 256>>>(bufA, bufB, B);
    }
    // linear
    linear_kernel<<<BT, 32>>>(bufB, wl, (float*)d_out);
}

// round 15
// speedup vs baseline: 1.0448x; 1.0448x over previous
#include <cuda_runtime.h>
#include <math.h>

#define THRESH 0.1f

typedef unsigned long long u64;

__device__ __forceinline__ u64 pack2(float lo, float hi) {
    u64 r;
    asm("mov.b64 %0, {%1, %2};" : "=l"(r) : "f"(lo), "f"(hi));
    return r;
}
__device__ __forceinline__ void unpack2(u64 v, float& lo, float& hi) {
    asm("mov.b64 {%0, %1}, %2;" : "=f"(lo), "=f"(hi) : "l"(v));
}
__device__ __forceinline__ u64 fma2(u64 a, u64 b, u64 c) {
    u64 d;
    asm("fma.rn.f32x2 %0, %1, %2, %3;" : "=l"(d) : "l"(a), "l"(b), "l"(c));
    return d;
}

// ---------------- scratch (no allocations allowed) ----------------
__device__ float g_bufA[26214400];
__device__ float g_bufB[13107200];
__device__ float g_w0[9 * 2 * 8];    // [k][ci][co]
__device__ float g_w1[9 * 8 * 16];
__device__ float g_w2[9 * 16 * 32];
__device__ float g_w3[9 * 32 * 64];
__device__ float g_wl[11 * 1024];

__global__ void noop_kernel() {}

// ---------------- fused weight norm (all layers, one launch) ----------------
__global__ void wnorm_all(const float* __restrict__ c0v, const float* __restrict__ c0g,
                          const float* __restrict__ c1v, const float* __restrict__ c1g,
                          const float* __restrict__ c2v, const float* __restrict__ c2g,
                          const float* __restrict__ c3v, const float* __restrict__ c3g,
                          const float* __restrict__ lv,  const float* __restrict__ lg,
                          float* __restrict__ w0, float* __restrict__ w1,
                          float* __restrict__ w2, float* __restrict__ w3,
                          float* __restrict__ wl) {
    int r = blockIdx.x;
    const float* v = 0; const float* g = 0; float* w = 0;
    int CIN = 0, COUT = 0, co = 0;
    bool lin = false;
    if (r < 8)        { v = c0v; g = c0g; w = w0; CIN = 2;  COUT = 8;  co = r; }
    else if (r < 24)  { v = c1v; g = c1g; w = w1; CIN = 8;  COUT = 16; co = r - 8; }
    else if (r < 56)  { v = c2v; g = c2g; w = w2; CIN = 16; COUT = 32; co = r - 24; }
    else if (r < 120) { v = c3v; g = c3g; w = w3; CIN = 32; COUT = 64; co = r - 56; }
    else              { lin = true; co = r - 120; }

    __shared__ float snorm;
    if (!lin) {
        const float* vr = v + (size_t)co * CIN * 9;
        if (threadIdx.x == 0) {
            float s = 0.f;
            for (int i = 0; i < CIN * 9; i++) s = __fadd_rn(s, __fmul_rn(vr[i], vr[i]));
            snorm = sqrtf(s);
        }
        __syncthreads();
        float norm = snorm, gg = g[co];
        for (int idx = threadIdx.x; idx < CIN * 9; idx += blockDim.x) {
            int ci = idx / 9, k = idx % 9;
            w[((size_t)k * CIN + ci) * COUT + co] = __fdiv_rn(__fmul_rn(gg, vr[idx]), norm);
        }
    } else {
        const float* vr = lv + (size_t)co * 1024;
        if (threadIdx.x == 0) {
            float s = 0.f;
            for (int i = 0; i < 1024; i++) s = __fadd_rn(s, __fmul_rn(vr[i], vr[i]));
            snorm = sqrtf(s);
        }
        __syncthreads();
        float norm = snorm, gg = lg[co];
        for (int i = threadIdx.x; i < 1024; i += blockDim.x)
            wl[(size_t)co * 1024 + i] = __fdiv_rn(__fmul_rn(gg, vr[i]), norm);
    }
}

// ---------------- layer 0 fully fused (v3 — proven at 558.7) ----------------
__global__ void __launch_bounds__(512) l0_fused(const float* __restrict__ x,
                                                const float* __restrict__ wt,
                                                float* __restrict__ out) {
    const int PW = 36, CPH = 18 * 36, BUFSZ = 2 * 18 * 36;
    __shared__ float sw[144];
    __shared__ float sin[2][BUFSZ];

    const int b = blockIdx.x >> 3;
    const int tile = blockIdx.x & 7;
    const int ty0 = (tile >> 1) * 16;
    const int tx0 = (tile & 1) * 32;
    const int tid = threadIdx.x;
    if (tid < 144) sw[tid] = wt[tid];

    const int cg = tid >> 7;
    const int ptid = tid & 127;
    const int py = ptid >> 4, px = ptid & 15;
    const int y0 = 2 * py, x0 = 2 * px;
    const int co0 = cg * 2;

    int srcOff[3], dstOff[3];
    bool ldOk[3], ldAct[3];
#pragma unroll
    for (int j = 0; j < 3; j++) {
        int i = tid + j * 512;
        bool act = i < 1224;
        int ii = act ? i : 0;
        int c = ii / 612;
        int r = ii - c * 612;
        int yy = r / 34, xx = r - yy * 34;
        int gy = ty0 + yy - 1, gx = tx0 + xx - 1;
        ldAct[j] = act;
        ldOk[j] = act && gy >= 0 && gy < 64 && gx >= 0 && gx < 64;
        srcOff[j] = c * 4096 + gy * 64 + gx;
        dstOff[j] = c * CPH + yy * PW + xx;
    }

    {
        const float* xp = x + ((size_t)(b * 50)) * 2 * 4096;
#pragma unroll
        for (int j = 0; j < 3; j++) {
            if (ldAct[j]) {
                float v = ldOk[j] ? xp[srcOff[j]] : 0.f;
                sin[0][dstOff[j]] = v;
            }
        }
    }

    float m[2][4];
#pragma unroll
    for (int c = 0; c < 2; c++) { m[c][0] = 0.f; m[c][1] = 0.f; m[c][2] = 0.f; m[c][3] = 0.f; }

    const int Y2 = (ty0 >> 1) + py, X2 = (tx0 >> 1) + px;

    int p = 0;
    for (int t = 0; t < 50; t++) {
        __syncthreads();

        const float* sbuf = sin[p];
        float inr[2][4][4];
#pragma unroll
        for (int ci = 0; ci < 2; ci++) {
#pragma unroll
            for (int r = 0; r < 4; r++) {
                const float* rp = sbuf + ci * CPH + (y0 + r) * PW + x0;
                float2 a = *reinterpret_cast<const float2*>(rp);
                float2 bb = *reinterpret_cast<const float2*>(rp + 2);
                inr[ci][r][0] = a.x; inr[ci][r][1] = a.y;
                inr[ci][r][2] = bb.x; inr[ci][r][3] = bb.y;
            }
        }

        if (t < 49) {
            const float* xp = x + ((size_t)(b * 50 + t + 1)) * 2 * 4096;
            float* dbuf = sin[p ^ 1];
#pragma unroll
            for (int j = 0; j < 3; j++) {
                if (ldAct[j]) {
                    float v = ldOk[j] ? xp[srcOff[j]] : 0.f;
                    dbuf[dstOff[j]] = v;
                }
            }
        }

        float acc[2][4];
#pragma unroll
        for (int c = 0; c < 2; c++) { acc[c][0] = 0.f; acc[c][1] = 0.f; acc[c][2] = 0.f; acc[c][3] = 0.f; }
#pragma unroll
        for (int ky = 0; ky < 3; ky++) {
#pragma unroll
            for (int kx = 0; kx < 3; kx++) {
#pragma unroll
                for (int ci = 0; ci < 2; ci++) {
                    float i00 = inr[ci][ky][kx];
                    float i01 = inr[ci][ky][kx + 1];
                    float i10 = inr[ci][ky + 1][kx];
                    float i11 = inr[ci][ky + 1][kx + 1];
                    const float2 wv = *reinterpret_cast<const float2*>(
                        sw + ((ky * 3 + kx) * 2 + ci) * 8 + co0);
                    acc[0][0] = __fmaf_rn(i00, wv.x, acc[0][0]);
                    acc[0][1] = __fmaf_rn(i01, wv.x, acc[0][1]);
                    acc[0][2] = __fmaf_rn(i10, wv.x, acc[0][2]);
                    acc[0][3] = __fmaf_rn(i11, wv.x, acc[0][3]);
                    acc[1][0] = __fmaf_rn(i00, wv.y, acc[1][0]);
                    acc[1][1] = __fmaf_rn(i01, wv.y, acc[1][1]);
                    acc[1][2] = __fmaf_rn(i10, wv.y, acc[1][2]);
                    acc[1][3] = __fmaf_rn(i11, wv.y, acc[1][3]);
                }
            }
        }

        float* op = out + ((size_t)(b * 50 + t) * 8 + co0) * 1024 + Y2 * 32 + X2;
#pragma unroll
        for (int c = 0; c < 2; c++) {
            float s = 0.f;
            m[c][0] = __fadd_rn(m[c][0], acc[c][0]);
            m[c][1] = __fadd_rn(m[c][1], acc[c][1]);
            m[c][2] = __fadd_rn(m[c][2], acc[c][2]);
            m[c][3] = __fadd_rn(m[c][3], acc[c][3]);
            if (m[c][0] >= THRESH) { m[c][0] = __fadd_rn(m[c][0], -THRESH); s += 0.25f; }
            if (m[c][1] >= THRESH) { m[c][1] = __fadd_rn(m[c][1], -THRESH); s += 0.25f; }
            if (m[c][2] >= THRESH) { m[c][2] = __fadd_rn(m[c][2], -THRESH); s += 0.25f; }
            if (m[c][3] >= THRESH) { m[c][3] = __fadd_rn(m[c][3], -THRESH); s += 0.25f; }
            op[c * 1024] = s;
        }
        p ^= 1;
    }
}

// ---------------- conv1 all-couts-per-thread: 8->16, 32x32 ----------------
// One pixel quad per thread, ALL 16 couts: input window loaded/packed ONCE per
// (tap,ci) and reused across 8 co-pairs. ci loop rolled (unroll 2) for I$.
// FMA chain per output exactly (ky,kx,ci), ci innermost — bit-identical.
__global__ void __launch_bounds__(256, 2)
conv1_allcg(const float* __restrict__ in, const float* __restrict__ wt,
            float* __restrict__ out) {
    const int W = 32, HW = 1024, PW = 34, PHW = 34 * 34, CIN = 8, COUT = 16;
    __shared__ float smem[CIN * PHW + 9 * CIN * COUT];   // 9248 + 1152 floats
    float* sin = smem;
    float* sw = smem + CIN * PHW;

    const int n = blockIdx.x;
    for (int i = threadIdx.x; i < CIN * PHW; i += 256) sin[i] = 0.f;
    for (int i = threadIdx.x; i < 9 * CIN * COUT; i += 256) sw[i] = wt[i];
    __syncthreads();
    for (int i = threadIdx.x; i < CIN * HW; i += 256) {
        int ci = i >> 10;
        int p = i & 1023;
        int y = p >> 5, x = p & 31;
        sin[ci * PHW + (y + 1) * PW + (x + 1)] = in[(size_t)n * CIN * HW + i];
    }
    __syncthreads();

    const int q = threadIdx.x;
    const int y2 = q >> 4, x2 = q & 15;
    const int y0 = 2 * y2, x0 = 2 * x2;

    u64 acc[8][4];
#pragma unroll
    for (int cp = 0; cp < 8; cp++) {
        acc[cp][0] = 0ULL; acc[cp][1] = 0ULL; acc[cp][2] = 0ULL; acc[cp][3] = 0ULL;
    }

#pragma unroll
    for (int ky = 0; ky < 3; ky++) {
#pragma unroll
        for (int kx = 0; kx < 3; kx++) {
            const float* ip = sin + (y0 + ky) * PW + (x0 + kx);
            const float* wpb = sw + (ky * 3 + kx) * CIN * COUT;
#pragma unroll 2
            for (int ci = 0; ci < CIN; ci++) {
                float i00, i01, i10, i11;
                if (kx != 1) {
                    float2 a = *reinterpret_cast<const float2*>(ip + ci * PHW);
                    float2 bb = *reinterpret_cast<const float2*>(ip + ci * PHW + PW);
                    i00 = a.x; i01 = a.y; i10 = bb.x; i11 = bb.y;
                } else {
                    i00 = ip[ci * PHW];
                    i01 = ip[ci * PHW + 1];
                    i10 = ip[ci * PHW + PW];
                    i11 = ip[ci * PHW + PW + 1];
                }
                u64 p00 = pack2(i00, i00);
                u64 p01 = pack2(i01, i01);
                u64 p10 = pack2(i10, i10);
                u64 p11 = pack2(i11, i11);
                const ulonglong2* wq = reinterpret_cast<const ulonglong2*>(wpb + ci * COUT);
                ulonglong2 wA = wq[0];   // co 0-3
                ulonglong2 wB = wq[1];   // co 4-7
                ulonglong2 wC = wq[2];   // co 8-11
                ulonglong2 wD = wq[3];   // co 12-15
                u64 ws[8] = {wA.x, wA.y, wB.x, wB.y, wC.x, wC.y, wD.x, wD.y};
#pragma unroll
                for (int cp = 0; cp < 8; cp++) {
                    acc[cp][0] = fma2(p00, ws[cp], acc[cp][0]);
                    acc[cp][1] = fma2(p01, ws[cp], acc[cp][1]);
                    acc[cp][2] = fma2(p10, ws[cp], acc[cp][2]);
                    acc[cp][3] = fma2(p11, ws[cp], acc[cp][3]);
                }
            }
        }
    }

    float* op = out + ((size_t)n * COUT) * HW + y0 * W + x0;
#pragma unroll
    for (int cp = 0; cp < 8; cp++) {
        float lo0, hi0, lo1, hi1, lo2, hi2, lo3, hi3;
        unpack2(acc[cp][0], lo0, hi0);
        unpack2(acc[cp][1], lo1, hi1);
        unpack2(acc[cp][2], lo2, hi2);
        unpack2(acc[cp][3], lo3, hi3);
        float* opc = op + (2 * cp) * HW;
        float2 r0; r0.x = lo0; r0.y = lo1;
        float2 r1; r1.x = lo2; r1.y = lo3;
        *reinterpret_cast<float2*>(opc) = r0;
        *reinterpret_cast<float2*>(opc + W) = r1;
        float* opc2 = op + (2 * cp + 1) * HW;
        float2 s0; s0.x = hi0; s0.y = hi1;
        float2 s1; s1.x = hi2; s1.y = hi3;
        *reinterpret_cast<float2*>(opc2) = s0;
        *reinterpret_cast<float2*>(opc2 + W) = s1;
    }
}

// ---------------- generic conv (conv2/conv3), packed f32x2 — R12 proven ----------------
template <int CIN, int COUT, int H, int IPB, int COG, int MINB>
__global__ void __launch_bounds__(256, MINB)
conv3x3_blk(const float* __restrict__ in, const float* __restrict__ wt,
            float* __restrict__ out) {
    const int W = H, HW = H * W, PW = W + 2, PHW = (H + 2) * PW;
    const int HW4 = HW / 4, W2 = W / 2;
    const int CPB = COUT / COG, NCG = CPB / 8;
    extern __shared__ float smem[];
    float* sin = smem;
    float* sw = smem + IPB * CIN * PHW;

    const int ngrp = blockIdx.x / COG;
    const int cog = blockIdx.x - ngrp * COG;
    const int coB = cog * CPB;
    const int n0 = ngrp * IPB;

    for (int i = threadIdx.x; i < IPB * CIN * PHW; i += blockDim.x) sin[i] = 0.f;
    if (COG == 1) {
        for (int i = threadIdx.x; i < 9 * CIN * CPB; i += blockDim.x) sw[i] = wt[i];
    } else {
        for (int i = threadIdx.x; i < 9 * CIN * CPB; i += blockDim.x) {
            int kci = i / CPB, c = i - kci * CPB;
            sw[i] = wt[kci * COUT + coB + c];
        }
    }
    __syncthreads();
    for (int i = threadIdx.x; i < IPB * CIN * HW; i += blockDim.x) {
        int img = i / (CIN * HW);
        int rem = i - img * (CIN * HW);
        int ci = rem / HW;
        int p = rem - ci * HW;
        int y = p / W;
        int x = p - y * W;
        sin[img * CIN * PHW + ci * PHW + (y + 1) * PW + (x + 1)] = in[(size_t)n0 * CIN * HW + i];
    }
    __syncthreads();

    const int ITEMS = IPB * HW4 * NCG;
    for (int item = threadIdx.x; item < ITEMS; item += blockDim.x) {
        int cg = item / (IPB * HW4);
        int rem = item - cg * (IPB * HW4);
        int img = rem / HW4;
        int q = rem - img * HW4;
        int y2 = q / W2, x2 = q - y2 * W2;
        int y0 = 2 * y2, x0 = 2 * x2;
        const float* simg = sin + img * CIN * PHW;

        u64 accP[4][4];
#pragma unroll
        for (int cp = 0; cp < 4; cp++) {
            accP[cp][0] = 0ULL; accP[cp][1] = 0ULL; accP[cp][2] = 0ULL; accP[cp][3] = 0ULL;
        }
#pragma unroll
        for (int ky = 0; ky < 3; ky++) {
#pragma unroll
            for (int kx = 0; kx < 3; kx++) {
                const float* ip = simg + (y0 + ky) * PW + (x0 + kx);
                const float* wp = sw + (ky * 3 + kx) * CIN * CPB + cg * 8;
#pragma unroll 4
                for (int ci = 0; ci < CIN; ci++) {
                    float i00, i01, i10, i11;
                    if (kx != 1) {
                        float2 a = *reinterpret_cast<const float2*>(ip + ci * PHW);
                        float2 bb = *reinterpret_cast<const float2*>(ip + ci * PHW + PW);
                        i00 = a.x; i01 = a.y; i10 = bb.x; i11 = bb.y;
                    } else {
                        i00 = ip[ci * PHW];
                        i01 = ip[ci * PHW + 1];
                        i10 = ip[ci * PHW + PW];
                        i11 = ip[ci * PHW + PW + 1];
                    }
                    u64 p00 = pack2(i00, i00);
                    u64 p01 = pack2(i01, i01);
                    u64 p10 = pack2(i10, i10);
                    u64 p11 = pack2(i11, i11);
                    const ulonglong2* wq2 = reinterpret_cast<const ulonglong2*>(wp + ci * CPB);
                    ulonglong2 wA = wq2[0];
                    ulonglong2 wB = wq2[1];
                    accP[0][0] = fma2(p00, wA.x, accP[0][0]);
                    accP[0][1] = fma2(p01, wA.x, accP[0][1]);
                    accP[0][2] = fma2(p10, wA.x, accP[0][2]);
                    accP[0][3] = fma2(p11, wA.x, accP[0][3]);
                    accP[1][0] = fma2(p00, wA.y, accP[1][0]);
                    accP[1][1] = fma2(p01, wA.y, accP[1][1]);
                    accP[1][2] = fma2(p10, wA.y, accP[1][2]);
                    accP[1][3] = fma2(p11, wA.y, accP[1][3]);
                    accP[2][0] = fma2(p00, wB.x, accP[2][0]);
                    accP[2][1] = fma2(p01, wB.x, accP[2][1]);
                    accP[2][2] = fma2(p10, wB.x, accP[2][2]);
                    accP[2][3] = fma2(p11, wB.x, accP[2][3]);
                    accP[3][0] = fma2(p00, wB.y, accP[3][0]);
                    accP[3][1] = fma2(p01, wB.y, accP[3][1]);
                    accP[3][2] = fma2(p10, wB.y, accP[3][2]);
                    accP[3][3] = fma2(p11, wB.y, accP[3][3]);
                }
            }
        }
        float* op = out + ((size_t)(n0 + img) * COUT + coB + cg * 8) * HW + y0 * W + x0;
#pragma unroll
        for (int cp = 0; cp < 4; cp++) {
            float lo0, hi0, lo1, hi1, lo2, hi2, lo3, hi3;
            unpack2(accP[cp][0], lo0, hi0);
            unpack2(accP[cp][1], lo1, hi1);
            unpack2(accP[cp][2], lo2, hi2);
            unpack2(accP[cp][3], lo3, hi3);
            float* opc = op + (2 * cp) * HW;
            float2 r0; r0.x = lo0; r0.y = lo1;
            float2 r1; r1.x = lo2; r1.y = lo3;
            *reinterpret_cast<float2*>(opc) = r0;
            *reinterpret_cast<float2*>(opc + W) = r1;
            float* opc2 = op + (2 * cp + 1) * HW;
            float2 s0; s0.x = hi0; s0.y = hi1;
            float2 s1; s1.x = hi2; s1.y = hi3;
            *reinterpret_cast<float2*>(opc2) = s0;
            *reinterpret_cast<float2*>(opc2 + W) = s1;
        }
    }
}

// ---------------- fused IAF + 2x2 avg pool: 2 pooled pixels / thread ----------------
template <int C, int H, int T>
__global__ void iaf_pool_kernel(const float* __restrict__ syn, float* __restrict__ out, int B) {
    const int W = H, HW = H * W, H2 = H / 2, W2 = W / 2, HW2 = H2 * W2, WP = W2 / 2;
    int idx = blockIdx.x * blockDim.x + threadIdx.x;
    int total = B * C * H2 * WP;
    if (idx >= total) return;
    int xp = idx % WP;
    int r = idx / WP;
    int y2 = r % H2;
    r /= H2;
    int c = r % C;
    int b = r / C;

    const size_t stride = (size_t)C * HW;
    const size_t ostride = (size_t)C * HW2;
    const float* p = syn + ((size_t)b * T) * stride + (size_t)c * HW + (size_t)(2 * y2) * W + 4 * xp;
    float* q = out + ((size_t)b * T) * ostride + (size_t)c * HW2 + (size_t)y2 * W2 + 2 * xp;

    float v0 = 0.f, v1 = 0.f, v2 = 0.f, v3 = 0.f;
    float u0 = 0.f, u1 = 0.f, u2 = 0.f, u3 = 0.f;
#pragma unroll 2
    for (int t = 0; t < T; t++) {
        const float4 a = *reinterpret_cast<const float4*>(p);
        const float4 bb = *reinterpret_cast<const float4*>(p + W);
        v0 = __fadd_rn(v0, a.x);
        v1 = __fadd_rn(v1, a.y);
        v2 = __fadd_rn(v2, bb.x);
        v3 = __fadd_rn(v3, bb.y);
        u0 = __fadd_rn(u0, a.z);
        u1 = __fadd_rn(u1, a.w);
        u2 = __fadd_rn(u2, bb.z);
        u3 = __fadd_rn(u3, bb.w);
        float s = 0.f, s2 = 0.f;
        if (v0 >= THRESH) { v0 = __fadd_rn(v0, -THRESH); s += 0.25f; }
        if (v1 >= THRESH) { v1 = __fadd_rn(v1, -THRESH); s += 0.25f; }
        if (v2 >= THRESH) { v2 = __fadd_rn(v2, -THRESH); s += 0.25f; }
        if (v3 >= THRESH) { v3 = __fadd_rn(v3, -THRESH); s += 0.25f; }
        if (u0 >= THRESH) { u0 = __fadd_rn(u0, -THRESH); s2 += 0.25f; }
        if (u1 >= THRESH) { u1 = __fadd_rn(u1, -THRESH); s2 += 0.25f; }
        if (u2 >= THRESH) { u2 = __fadd_rn(u2, -THRESH); s2 += 0.25f; }
        if (u3 >= THRESH) { u3 = __fadd_rn(u3, -THRESH); s2 += 0.25f; }
        float2 sv; sv.x = s; sv.y = s2;
        *reinterpret_cast<float2*>(q) = sv;
        p += stride;
        q += ostride;
    }
}

// ---------------- final linear: (BT,1024) @ (11,1024)^T ----------------
__global__ void linear_kernel(const float* __restrict__ in, const float* __restrict__ w,
                              float* __restrict__ out) {
    int n = blockIdx.x;
    __shared__ float srow[1024];
    for (int i = threadIdx.x; i < 1024; i += blockDim.x) srow[i] = in[(size_t)n * 1024 + i];
    __syncthreads();
    int cls = threadIdx.x;
    if (cls >= 11) return;
    const float* wr = w + (size_t)cls * 1024;
    float acc = 0.f;
    for (int i = 0; i < 1024; i++) acc = __fmaf_rn(srow[i], wr[i], acc);
    out[(size_t)n * 11 + cls] = acc;
}

extern "C" void kernel_launch(void* const* d_in, const int* in_sizes, int n_in,
                              void* d_out, int out_size) {
    const float* x   = (const float*)d_in[0];
    const float* c0v = (const float*)d_in[1];
    const float* c0g = (const float*)d_in[2];
    const float* c1v = (const float*)d_in[3];
    const float* c1g = (const float*)d_in[4];
    const float* c2v = (const float*)d_in[5];
    const float* c2g = (const float*)d_in[6];
    const float* c3v = (const float*)d_in[7];
    const float* c3g = (const float*)d_in[8];
    const float* lv  = (const float*)d_in[9];
    const float* lg  = (const float*)d_in[10];

    float *bufA, *bufB, *w0, *w1, *w2, *w3, *wl;
    cudaGetSymbolAddress((void**)&bufA, g_bufA);
    cudaGetSymbolAddress((void**)&bufB, g_bufB);
    cudaGetSymbolAddress((void**)&w0, g_w0);
    cudaGetSymbolAddress((void**)&w1, g_w1);
    cudaGetSymbolAddress((void**)&w2, g_w2);
    cudaGetSymbolAddress((void**)&w3, g_w3);
    cudaGetSymbolAddress((void**)&wl, g_wl);

    const int B = 32, T = 50, BT = B * T;

    // (1) weight norms
    wnorm_all<<<131, 64>>>(c0v, c0g, c1v, c1g, c2v, c2g, c3v, c3g, lv, lg,
                           w0, w1, w2, w3, wl);

    const int smem2 = (2 * 16 * 18 * 18 + 9 * 16 * 32) * 4;    // 59904
    const int smem3 = (2 * 32 * 10 * 10 + 9 * 32 * 32) * 4;    // 62464 (COG=2)

    cudaFuncSetAttribute((const void*)conv3x3_blk<16, 32, 16, 2, 1, 4>,
                         cudaFuncAttributeMaxDynamicSharedMemorySize, smem2);
    cudaFuncSetAttribute((const void*)conv3x3_blk<32, 64, 8, 2, 2, 3>,
                         cudaFuncAttributeMaxDynamicSharedMemorySize, smem3);

    // (2) layer 0 fused (v3)
    l0_fused<<<B * 8, 512>>>(x, w0, bufB);
    // (3) alignment no-op so conv1 is the 4th launch
    noop_kernel<<<1, 32>>>();

    // (4) layer 1 conv — all-cg kernel
    conv1_allcg<<<BT, 256>>>(bufB, w1, bufA);
    {
        int total = B * 16 * 16 * 8;
        iaf_pool_kernel<16, 32, 50><<<(total + 255) / 256, 256>>>(bufA, bufB, B);
    }
    // layer 2
    conv3x3_blk<16, 32, 16, 2, 1, 4><<<BT / 2, 256, smem2>>>(bufB, w2, bufA);
    {
        int total = B * 32 * 8 * 4;
        iaf_pool_kernel<32, 16, 50><<<(total + 255) / 256, 256>>>(bufA, bufB, B);
    }
    // layer 3 (COG=2)
    conv3x3_blk<32, 64, 8, 2, 2, 3><<<BT, 256, smem3>>>(bufB, w3, bufA);
    {
        int total = B * 64 * 4 * 2;
        iaf_pool_kernel<64, 8, 50><<<(total + 255) / 256, 256>>>(bufA, bufB, B);
    }
    // linear
    linear_kernel<<<BT, 32>>>(bufB, wl, (float*)d_out);
}

// round 16
// speedup vs baseline: 1.0930x; 1.0462x over previous
#include <cuda_runtime.h>
#include <math.h>

#define THRESH 0.1f

typedef unsigned long long u64;

__device__ __forceinline__ u64 pack2(float lo, float hi) {
    u64 r;
    asm("mov.b64 %0, {%1, %2};" : "=l"(r) : "f"(lo), "f"(hi));
    return r;
}
__device__ __forceinline__ void unpack2(u64 v, float& lo, float& hi) {
    asm("mov.b64 {%0, %1}, %2;" : "=f"(lo), "=f"(hi) : "l"(v));
}
__device__ __forceinline__ u64 fma2(u64 a, u64 b, u64 c) {
    u64 d;
    asm("fma.rn.f32x2 %0, %1, %2, %3;" : "=l"(d) : "l"(a), "l"(b), "l"(c));
    return d;
}

// ---------------- scratch (no allocations allowed) ----------------
__device__ float g_bufA[26214400];
__device__ float g_bufB[13107200];
__device__ float g_w0[9 * 2 * 8];    // [k][ci][co]
__device__ float g_w1[9 * 8 * 16];
__device__ float g_w2[9 * 16 * 32];
__device__ float g_w3[9 * 32 * 64];
__device__ float g_wl[11 * 1024];

__global__ void noop_kernel() {}

// ---------------- fused weight norm (all layers, one launch) ----------------
__global__ void wnorm_all(const float* __restrict__ c0v, const float* __restrict__ c0g,
                          const float* __restrict__ c1v, const float* __restrict__ c1g,
                          const float* __restrict__ c2v, const float* __restrict__ c2g,
                          const float* __restrict__ c3v, const float* __restrict__ c3g,
                          const float* __restrict__ lv,  const float* __restrict__ lg,
                          float* __restrict__ w0, float* __restrict__ w1,
                          float* __restrict__ w2, float* __restrict__ w3,
                          float* __restrict__ wl) {
    int r = blockIdx.x;
    const float* v = 0; const float* g = 0; float* w = 0;
    int CIN = 0, COUT = 0, co = 0;
    bool lin = false;
    if (r < 8)        { v = c0v; g = c0g; w = w0; CIN = 2;  COUT = 8;  co = r; }
    else if (r < 24)  { v = c1v; g = c1g; w = w1; CIN = 8;  COUT = 16; co = r - 8; }
    else if (r < 56)  { v = c2v; g = c2g; w = w2; CIN = 16; COUT = 32; co = r - 24; }
    else if (r < 120) { v = c3v; g = c3g; w = w3; CIN = 32; COUT = 64; co = r - 56; }
    else              { lin = true; co = r - 120; }

    __shared__ float snorm;
    if (!lin) {
        const float* vr = v + (size_t)co * CIN * 9;
        if (threadIdx.x == 0) {
            float s = 0.f;
            for (int i = 0; i < CIN * 9; i++) s = __fadd_rn(s, __fmul_rn(vr[i], vr[i]));
            snorm = sqrtf(s);
        }
        __syncthreads();
        float norm = snorm, gg = g[co];
        for (int idx = threadIdx.x; idx < CIN * 9; idx += blockDim.x) {
            int ci = idx / 9, k = idx % 9;
            w[((size_t)k * CIN + ci) * COUT + co] = __fdiv_rn(__fmul_rn(gg, vr[idx]), norm);
        }
    } else {
        const float* vr = lv + (size_t)co * 1024;
        if (threadIdx.x == 0) {
            float s = 0.f;
            for (int i = 0; i < 1024; i++) s = __fadd_rn(s, __fmul_rn(vr[i], vr[i]));
            snorm = sqrtf(s);
        }
        __syncthreads();
        float norm = snorm, gg = lg[co];
        for (int i = threadIdx.x; i < 1024; i += blockDim.x)
            wl[(size_t)co * 1024 + i] = __fdiv_rn(__fmul_rn(gg, vr[i]), norm);
    }
}

// ---------------- layer 0 fully fused (v3 — proven) ----------------
__global__ void __launch_bounds__(512) l0_fused(const float* __restrict__ x,
                                                const float* __restrict__ wt,
                                                float* __restrict__ out) {
    const int PW = 36, CPH = 18 * 36, BUFSZ = 2 * 18 * 36;
    __shared__ float sw[144];
    __shared__ float sin[2][BUFSZ];

    const int b = blockIdx.x >> 3;
    const int tile = blockIdx.x & 7;
    const int ty0 = (tile >> 1) * 16;
    const int tx0 = (tile & 1) * 32;
    const int tid = threadIdx.x;
    if (tid < 144) sw[tid] = wt[tid];

    const int cg = tid >> 7;
    const int ptid = tid & 127;
    const int py = ptid >> 4, px = ptid & 15;
    const int y0 = 2 * py, x0 = 2 * px;
    const int co0 = cg * 2;

    int srcOff[3], dstOff[3];
    bool ldOk[3], ldAct[3];
#pragma unroll
    for (int j = 0; j < 3; j++) {
        int i = tid + j * 512;
        bool act = i < 1224;
        int ii = act ? i : 0;
        int c = ii / 612;
        int r = ii - c * 612;
        int yy = r / 34, xx = r - yy * 34;
        int gy = ty0 + yy - 1, gx = tx0 + xx - 1;
        ldAct[j] = act;
        ldOk[j] = act && gy >= 0 && gy < 64 && gx >= 0 && gx < 64;
        srcOff[j] = c * 4096 + gy * 64 + gx;
        dstOff[j] = c * CPH + yy * PW + xx;
    }

    {
        const float* xp = x + ((size_t)(b * 50)) * 2 * 4096;
#pragma unroll
        for (int j = 0; j < 3; j++) {
            if (ldAct[j]) {
                float v = ldOk[j] ? xp[srcOff[j]] : 0.f;
                sin[0][dstOff[j]] = v;
            }
        }
    }

    float m[2][4];
#pragma unroll
    for (int c = 0; c < 2; c++) { m[c][0] = 0.f; m[c][1] = 0.f; m[c][2] = 0.f; m[c][3] = 0.f; }

    const int Y2 = (ty0 >> 1) + py, X2 = (tx0 >> 1) + px;

    int p = 0;
    for (int t = 0; t < 50; t++) {
        __syncthreads();

        const float* sbuf = sin[p];
        float inr[2][4][4];
#pragma unroll
        for (int ci = 0; ci < 2; ci++) {
#pragma unroll
            for (int r = 0; r < 4; r++) {
                const float* rp = sbuf + ci * CPH + (y0 + r) * PW + x0;
                float2 a = *reinterpret_cast<const float2*>(rp);
                float2 bb = *reinterpret_cast<const float2*>(rp + 2);
                inr[ci][r][0] = a.x; inr[ci][r][1] = a.y;
                inr[ci][r][2] = bb.x; inr[ci][r][3] = bb.y;
            }
        }

        if (t < 49) {
            const float* xp = x + ((size_t)(b * 50 + t + 1)) * 2 * 4096;
            float* dbuf = sin[p ^ 1];
#pragma unroll
            for (int j = 0; j < 3; j++) {
                if (ldAct[j]) {
                    float v = ldOk[j] ? xp[srcOff[j]] : 0.f;
                    dbuf[dstOff[j]] = v;
                }
            }
        }

        float acc[2][4];
#pragma unroll
        for (int c = 0; c < 2; c++) { acc[c][0] = 0.f; acc[c][1] = 0.f; acc[c][2] = 0.f; acc[c][3] = 0.f; }
#pragma unroll
        for (int ky = 0; ky < 3; ky++) {
#pragma unroll
            for (int kx = 0; kx < 3; kx++) {
#pragma unroll
                for (int ci = 0; ci < 2; ci++) {
                    float i00 = inr[ci][ky][kx];
                    float i01 = inr[ci][ky][kx + 1];
                    float i10 = inr[ci][ky + 1][kx];
                    float i11 = inr[ci][ky + 1][kx + 1];
                    const float2 wv = *reinterpret_cast<const float2*>(
                        sw + ((ky * 3 + kx) * 2 + ci) * 8 + co0);
                    acc[0][0] = __fmaf_rn(i00, wv.x, acc[0][0]);
                    acc[0][1] = __fmaf_rn(i01, wv.x, acc[0][1]);
                    acc[0][2] = __fmaf_rn(i10, wv.x, acc[0][2]);
                    acc[0][3] = __fmaf_rn(i11, wv.x, acc[0][3]);
                    acc[1][0] = __fmaf_rn(i00, wv.y, acc[1][0]);
                    acc[1][1] = __fmaf_rn(i01, wv.y, acc[1][1]);
                    acc[1][2] = __fmaf_rn(i10, wv.y, acc[1][2]);
                    acc[1][3] = __fmaf_rn(i11, wv.y, acc[1][3]);
                }
            }
        }

        float* op = out + ((size_t)(b * 50 + t) * 8 + co0) * 1024 + Y2 * 32 + X2;
#pragma unroll
        for (int c = 0; c < 2; c++) {
            float s = 0.f;
            m[c][0] = __fadd_rn(m[c][0], acc[c][0]);
            m[c][1] = __fadd_rn(m[c][1], acc[c][1]);
            m[c][2] = __fadd_rn(m[c][2], acc[c][2]);
            m[c][3] = __fadd_rn(m[c][3], acc[c][3]);
            if (m[c][0] >= THRESH) { m[c][0] = __fadd_rn(m[c][0], -THRESH); s += 0.25f; }
            if (m[c][1] >= THRESH) { m[c][1] = __fadd_rn(m[c][1], -THRESH); s += 0.25f; }
            if (m[c][2] >= THRESH) { m[c][2] = __fadd_rn(m[c][2], -THRESH); s += 0.25f; }
            if (m[c][3] >= THRESH) { m[c][3] = __fadd_rn(m[c][3], -THRESH); s += 0.25f; }
            op[c * 1024] = s;
        }
        p ^= 1;
    }
}

// ---------------- conv1 all-couts: 8->16, 32x32 (R15 proven, 86us) ----------------
__global__ void __launch_bounds__(256, 2)
conv1_allcg(const float* __restrict__ in, const float* __restrict__ wt,
            float* __restrict__ out) {
    const int W = 32, HW = 1024, PW = 34, PHW = 34 * 34, CIN = 8, COUT = 16;
    __shared__ float smem[CIN * PHW + 9 * CIN * COUT];
    float* sin = smem;
    float* sw = smem + CIN * PHW;

    const int n = blockIdx.x;
    for (int i = threadIdx.x; i < CIN * PHW; i += 256) sin[i] = 0.f;
    for (int i = threadIdx.x; i < 9 * CIN * COUT; i += 256) sw[i] = wt[i];
    __syncthreads();
    for (int i = threadIdx.x; i < CIN * HW; i += 256) {
        int ci = i >> 10;
        int p = i & 1023;
        int y = p >> 5, x = p & 31;
        sin[ci * PHW + (y + 1) * PW + (x + 1)] = in[(size_t)n * CIN * HW + i];
    }
    __syncthreads();

    const int q = threadIdx.x;
    const int y2 = q >> 4, x2 = q & 15;
    const int y0 = 2 * y2, x0 = 2 * x2;

    u64 acc[8][4];
#pragma unroll
    for (int cp = 0; cp < 8; cp++) {
        acc[cp][0] = 0ULL; acc[cp][1] = 0ULL; acc[cp][2] = 0ULL; acc[cp][3] = 0ULL;
    }

#pragma unroll
    for (int ky = 0; ky < 3; ky++) {
#pragma unroll
        for (int kx = 0; kx < 3; kx++) {
            const float* ip = sin + (y0 + ky) * PW + (x0 + kx);
            const float* wpb = sw + (ky * 3 + kx) * CIN * COUT;
#pragma unroll 2
            for (int ci = 0; ci < CIN; ci++) {
                float i00, i01, i10, i11;
                if (kx != 1) {
                    float2 a = *reinterpret_cast<const float2*>(ip + ci * PHW);
                    float2 bb = *reinterpret_cast<const float2*>(ip + ci * PHW + PW);
                    i00 = a.x; i01 = a.y; i10 = bb.x; i11 = bb.y;
                } else {
                    i00 = ip[ci * PHW];
                    i01 = ip[ci * PHW + 1];
                    i10 = ip[ci * PHW + PW];
                    i11 = ip[ci * PHW + PW + 1];
                }
                u64 p00 = pack2(i00, i00);
                u64 p01 = pack2(i01, i01);
                u64 p10 = pack2(i10, i10);
                u64 p11 = pack2(i11, i11);
                const ulonglong2* wq = reinterpret_cast<const ulonglong2*>(wpb + ci * COUT);
                ulonglong2 wA = wq[0];
                ulonglong2 wB = wq[1];
                ulonglong2 wC = wq[2];
                ulonglong2 wD = wq[3];
                u64 ws[8] = {wA.x, wA.y, wB.x, wB.y, wC.x, wC.y, wD.x, wD.y};
#pragma unroll
                for (int cp = 0; cp < 8; cp++) {
                    acc[cp][0] = fma2(p00, ws[cp], acc[cp][0]);
                    acc[cp][1] = fma2(p01, ws[cp], acc[cp][1]);
                    acc[cp][2] = fma2(p10, ws[cp], acc[cp][2]);
                    acc[cp][3] = fma2(p11, ws[cp], acc[cp][3]);
                }
            }
        }
    }

    float* op = out + ((size_t)n * COUT) * HW + y0 * W + x0;
#pragma unroll
    for (int cp = 0; cp < 8; cp++) {
        float lo0, hi0, lo1, hi1, lo2, hi2, lo3, hi3;
        unpack2(acc[cp][0], lo0, hi0);
        unpack2(acc[cp][1], lo1, hi1);
        unpack2(acc[cp][2], lo2, hi2);
        unpack2(acc[cp][3], lo3, hi3);
        float* opc = op + (2 * cp) * HW;
        float2 r0; r0.x = lo0; r0.y = lo1;
        float2 r1; r1.x = lo2; r1.y = lo3;
        *reinterpret_cast<float2*>(opc) = r0;
        *reinterpret_cast<float2*>(opc + W) = r1;
        float* opc2 = op + (2 * cp + 1) * HW;
        float2 s0; s0.x = hi0; s0.y = hi1;
        float2 s1; s1.x = hi2; s1.y = hi3;
        *reinterpret_cast<float2*>(opc2) = s0;
        *reinterpret_cast<float2*>(opc2 + W) = s1;
    }
}

// ---------------- conv2: 16->32, 16x16, 16 couts/thread, 2 images/block ----------------
// Item = (cout-half, image, quad): 2*2*64 = 256 = 1/thread. Input window loaded
// and packed ONCE per (tap,ci), reused for 8 co-pairs. Chain (ky,kx,ci) exact.
__global__ void __launch_bounds__(256, 2)
conv2_allcg(const float* __restrict__ in, const float* __restrict__ wt,
            float* __restrict__ out) {
    const int W = 16, HW = 256, PW = 18, PHW = 18 * 18, CIN = 16, COUT = 32;
    extern __shared__ float smem[];
    float* sin = smem;                      // 2*16*324 = 10368
    float* sw = smem + 2 * CIN * PHW;       // 9*16*32 = 4608

    const int n0 = blockIdx.x * 2;
    for (int i = threadIdx.x; i < 2 * CIN * PHW; i += 256) sin[i] = 0.f;
    for (int i = threadIdx.x; i < 9 * CIN * COUT; i += 256) sw[i] = wt[i];
    __syncthreads();
    for (int i = threadIdx.x; i < 2 * CIN * HW; i += 256) {
        int img = i >> 12;
        int rem = i & 4095;
        int ci = rem >> 8;
        int p = rem & 255;
        int y = p >> 4, x = p & 15;
        sin[img * CIN * PHW + ci * PHW + (y + 1) * PW + (x + 1)] = in[(size_t)n0 * CIN * HW + i];
    }
    __syncthreads();

    const int cg = threadIdx.x >> 7;          // cout half: couts cg*16..+15
    const int img = (threadIdx.x >> 6) & 1;
    const int q = threadIdx.x & 63;
    const int y2 = q >> 3, x2 = q & 7;
    const int y0 = 2 * y2, x0 = 2 * x2;
    const float* simg = sin + img * CIN * PHW;

    u64 acc[8][4];
#pragma unroll
    for (int cp = 0; cp < 8; cp++) {
        acc[cp][0] = 0ULL; acc[cp][1] = 0ULL; acc[cp][2] = 0ULL; acc[cp][3] = 0ULL;
    }

#pragma unroll
    for (int ky = 0; ky < 3; ky++) {
#pragma unroll
        for (int kx = 0; kx < 3; kx++) {
            const float* ip = simg + (y0 + ky) * PW + (x0 + kx);
            const float* wpb = sw + (ky * 3 + kx) * CIN * COUT + cg * 16;
#pragma unroll 4
            for (int ci = 0; ci < CIN; ci++) {
                float i00, i01, i10, i11;
                if (kx != 1) {
                    float2 a = *reinterpret_cast<const float2*>(ip + ci * PHW);
                    float2 bb = *reinterpret_cast<const float2*>(ip + ci * PHW + PW);
                    i00 = a.x; i01 = a.y; i10 = bb.x; i11 = bb.y;
                } else {
                    i00 = ip[ci * PHW];
                    i01 = ip[ci * PHW + 1];
                    i10 = ip[ci * PHW + PW];
                    i11 = ip[ci * PHW + PW + 1];
                }
                u64 p00 = pack2(i00, i00);
                u64 p01 = pack2(i01, i01);
                u64 p10 = pack2(i10, i10);
                u64 p11 = pack2(i11, i11);
                const ulonglong2* wq = reinterpret_cast<const ulonglong2*>(wpb + ci * COUT);
                ulonglong2 wA = wq[0];
                ulonglong2 wB = wq[1];
                ulonglong2 wC = wq[2];
                ulonglong2 wD = wq[3];
                u64 ws[8] = {wA.x, wA.y, wB.x, wB.y, wC.x, wC.y, wD.x, wD.y};
#pragma unroll
                for (int cp = 0; cp < 8; cp++) {
                    acc[cp][0] = fma2(p00, ws[cp], acc[cp][0]);
                    acc[cp][1] = fma2(p01, ws[cp], acc[cp][1]);
                    acc[cp][2] = fma2(p10, ws[cp], acc[cp][2]);
                    acc[cp][3] = fma2(p11, ws[cp], acc[cp][3]);
                }
            }
        }
    }

    float* op = out + ((size_t)(n0 + img) * COUT + cg * 16) * HW + y0 * W + x0;
#pragma unroll
    for (int cp = 0; cp < 8; cp++) {
        float lo0, hi0, lo1, hi1, lo2, hi2, lo3, hi3;
        unpack2(acc[cp][0], lo0, hi0);
        unpack2(acc[cp][1], lo1, hi1);
        unpack2(acc[cp][2], lo2, hi2);
        unpack2(acc[cp][3], lo3, hi3);
        float* opc = op + (2 * cp) * HW;
        float2 r0; r0.x = lo0; r0.y = lo1;
        float2 r1; r1.x = lo2; r1.y = lo3;
        *reinterpret_cast<float2*>(opc) = r0;
        *reinterpret_cast<float2*>(opc + W) = r1;
        float* opc2 = op + (2 * cp + 1) * HW;
        float2 s0; s0.x = hi0; s0.y = hi1;
        float2 s1; s1.x = hi2; s1.y = hi3;
        *reinterpret_cast<float2*>(opc2) = s0;
        *reinterpret_cast<float2*>(opc2 + W) = s1;
    }
}

// ---------------- generic conv (conv3), packed f32x2 ----------------
template <int CIN, int COUT, int H, int IPB, int COG, int MINB>
__global__ void __launch_bounds__(256, MINB)
conv3x3_blk(const float* __restrict__ in, const float* __restrict__ wt,
            float* __restrict__ out) {
    const int W = H, HW = H * W, PW = W + 2, PHW = (H + 2) * PW;
    const int HW4 = HW / 4, W2 = W / 2;
    const int CPB = COUT / COG, NCG = CPB / 8;
    extern __shared__ float smem[];
    float* sin = smem;
    float* sw = smem + IPB * CIN * PHW;

    const int ngrp = blockIdx.x / COG;
    const int cog = blockIdx.x - ngrp * COG;
    const int coB = cog * CPB;
    const int n0 = ngrp * IPB;

    for (int i = threadIdx.x; i < IPB * CIN * PHW; i += blockDim.x) sin[i] = 0.f;
    if (COG == 1) {
        for (int i = threadIdx.x; i < 9 * CIN * CPB; i += blockDim.x) sw[i] = wt[i];
    } else {
        for (int i = threadIdx.x; i < 9 * CIN * CPB; i += blockDim.x) {
            int kci = i / CPB, c = i - kci * CPB;
            sw[i] = wt[kci * COUT + coB + c];
        }
    }
    __syncthreads();
    for (int i = threadIdx.x; i < IPB * CIN * HW; i += blockDim.x) {
        int img = i / (CIN * HW);
        int rem = i - img * (CIN * HW);
        int ci = rem / HW;
        int p = rem - ci * HW;
        int y = p / W;
        int x = p - y * W;
        sin[img * CIN * PHW + ci * PHW + (y + 1) * PW + (x + 1)] = in[(size_t)n0 * CIN * HW + i];
    }
    __syncthreads();

    const int ITEMS = IPB * HW4 * NCG;
    for (int item = threadIdx.x; item < ITEMS; item += blockDim.x) {
        int cg = item / (IPB * HW4);
        int rem = item - cg * (IPB * HW4);
        int img = rem / HW4;
        int q = rem - img * HW4;
        int y2 = q / W2, x2 = q - y2 * W2;
        int y0 = 2 * y2, x0 = 2 * x2;
        const float* simg = sin + img * CIN * PHW;

        u64 accP[4][4];
#pragma unroll
        for (int cp = 0; cp < 4; cp++) {
            accP[cp][0] = 0ULL; accP[cp][1] = 0ULL; accP[cp][2] = 0ULL; accP[cp][3] = 0ULL;
        }
#pragma unroll
        for (int ky = 0; ky < 3; ky++) {
#pragma unroll
            for (int kx = 0; kx < 3; kx++) {
                const float* ip = simg + (y0 + ky) * PW + (x0 + kx);
                const float* wp = sw + (ky * 3 + kx) * CIN * CPB + cg * 8;
#pragma unroll 4
                for (int ci = 0; ci < CIN; ci++) {
                    float i00, i01, i10, i11;
                    if (kx != 1) {
                        float2 a = *reinterpret_cast<const float2*>(ip + ci * PHW);
                        float2 bb = *reinterpret_cast<const float2*>(ip + ci * PHW + PW);
                        i00 = a.x; i01 = a.y; i10 = bb.x; i11 = bb.y;
                    } else {
                        i00 = ip[ci * PHW];
                        i01 = ip[ci * PHW + 1];
                        i10 = ip[ci * PHW + PW];
                        i11 = ip[ci * PHW + PW + 1];
                    }
                    u64 p00 = pack2(i00, i00);
                    u64 p01 = pack2(i01, i01);
                    u64 p10 = pack2(i10, i10);
                    u64 p11 = pack2(i11, i11);
                    const ulonglong2* wq2 = reinterpret_cast<const ulonglong2*>(wp + ci * CPB);
                    ulonglong2 wA = wq2[0];
                    ulonglong2 wB = wq2[1];
                    accP[0][0] = fma2(p00, wA.x, accP[0][0]);
                    accP[0][1] = fma2(p01, wA.x, accP[0][1]);
                    accP[0][2] = fma2(p10, wA.x, accP[0][2]);
                    accP[0][3] = fma2(p11, wA.x, accP[0][3]);
                    accP[1][0] = fma2(p00, wA.y, accP[1][0]);
                    accP[1][1] = fma2(p01, wA.y, accP[1][1]);
                    accP[1][2] = fma2(p10, wA.y, accP[1][2]);
                    accP[1][3] = fma2(p11, wA.y, accP[1][3]);
                    accP[2][0] = fma2(p00, wB.x, accP[2][0]);
                    accP[2][1] = fma2(p01, wB.x, accP[2][1]);
                    accP[2][2] = fma2(p10, wB.x, accP[2][2]);
                    accP[2][3] = fma2(p11, wB.x, accP[2][3]);
                    accP[3][0] = fma2(p00, wB.y, accP[3][0]);
                    accP[3][1] = fma2(p01, wB.y, accP[3][1]);
                    accP[3][2] = fma2(p10, wB.y, accP[3][2]);
                    accP[3][3] = fma2(p11, wB.y, accP[3][3]);
                }
            }
        }
        float* op = out + ((size_t)(n0 + img) * COUT + coB + cg * 8) * HW + y0 * W + x0;
#pragma unroll
        for (int cp = 0; cp < 4; cp++) {
            float lo0, hi0, lo1, hi1, lo2, hi2, lo3, hi3;
            unpack2(accP[cp][0], lo0, hi0);
            unpack2(accP[cp][1], lo1, hi1);
            unpack2(accP[cp][2], lo2, hi2);
            unpack2(accP[cp][3], lo3, hi3);
            float* opc = op + (2 * cp) * HW;
            float2 r0; r0.x = lo0; r0.y = lo1;
            float2 r1; r1.x = lo2; r1.y = lo3;
            *reinterpret_cast<float2*>(opc) = r0;
            *reinterpret_cast<float2*>(opc + W) = r1;
            float* opc2 = op + (2 * cp + 1) * HW;
            float2 s0; s0.x = hi0; s0.y = hi1;
            float2 s1; s1.x = hi2; s1.y = hi3;
            *reinterpret_cast<float2*>(opc2) = s0;
            *reinterpret_cast<float2*>(opc2 + W) = s1;
        }
    }
}

// ---------------- fused IAF + 2x2 avg pool: 2 pooled pixels / thread ----------------
template <int C, int H, int T>
__global__ void iaf_pool_kernel(const float* __restrict__ syn, float* __restrict__ out, int B) {
    const int W = H, HW = H * W, H2 = H / 2, W2 = W / 2, HW2 = H2 * W2, WP = W2 / 2;
    int idx = blockIdx.x * blockDim.x + threadIdx.x;
    int total = B * C * H2 * WP;
    if (idx >= total) return;
    int xp = idx % WP;
    int r = idx / WP;
    int y2 = r % H2;
    r /= H2;
    int c = r % C;
    int b = r / C;

    const size_t stride = (size_t)C * HW;
    const size_t ostride = (size_t)C * HW2;
    const float* p = syn + ((size_t)b * T) * stride + (size_t)c * HW + (size_t)(2 * y2) * W + 4 * xp;
    float* q = out + ((size_t)b * T) * ostride + (size_t)c * HW2 + (size_t)y2 * W2 + 2 * xp;

    float v0 = 0.f, v1 = 0.f, v2 = 0.f, v3 = 0.f;
    float u0 = 0.f, u1 = 0.f, u2 = 0.f, u3 = 0.f;
#pragma unroll 2
    for (int t = 0; t < T; t++) {
        const float4 a = *reinterpret_cast<const float4*>(p);
        const float4 bb = *reinterpret_cast<const float4*>(p + W);
        v0 = __fadd_rn(v0, a.x);
        v1 = __fadd_rn(v1, a.y);
        v2 = __fadd_rn(v2, bb.x);
        v3 = __fadd_rn(v3, bb.y);
        u0 = __fadd_rn(u0, a.z);
        u1 = __fadd_rn(u1, a.w);
        u2 = __fadd_rn(u2, bb.z);
        u3 = __fadd_rn(u3, bb.w);
        float s = 0.f, s2 = 0.f;
        if (v0 >= THRESH) { v0 = __fadd_rn(v0, -THRESH); s += 0.25f; }
        if (v1 >= THRESH) { v1 = __fadd_rn(v1, -THRESH); s += 0.25f; }
        if (v2 >= THRESH) { v2 = __fadd_rn(v2, -THRESH); s += 0.25f; }
        if (v3 >= THRESH) { v3 = __fadd_rn(v3, -THRESH); s += 0.25f; }
        if (u0 >= THRESH) { u0 = __fadd_rn(u0, -THRESH); s2 += 0.25f; }
        if (u1 >= THRESH) { u1 = __fadd_rn(u1, -THRESH); s2 += 0.25f; }
        if (u2 >= THRESH) { u2 = __fadd_rn(u2, -THRESH); s2 += 0.25f; }
        if (u3 >= THRESH) { u3 = __fadd_rn(u3, -THRESH); s2 += 0.25f; }
        float2 sv; sv.x = s; sv.y = s2;
        *reinterpret_cast<float2*>(q) = sv;
        p += stride;
        q += ostride;
    }
}

// ---------------- final linear: (BT,1024) @ (11,1024)^T ----------------
__global__ void linear_kernel(const float* __restrict__ in, const float* __restrict__ w,
                              float* __restrict__ out) {
    int n = blockIdx.x;
    __shared__ float srow[1024];
    for (int i = threadIdx.x; i < 1024; i += blockDim.x) srow[i] = in[(size_t)n * 1024 + i];
    __syncthreads();
    int cls = threadIdx.x;
    if (cls >= 11) return;
    const float* wr = w + (size_t)cls * 1024;
    float acc = 0.f;
    for (int i = 0; i < 1024; i++) acc = __fmaf_rn(srow[i], wr[i], acc);
    out[(size_t)n * 11 + cls] = acc;
}

extern "C" void kernel_launch(void* const* d_in, const int* in_sizes, int n_in,
                              void* d_out, int out_size) {
    const float* x   = (const float*)d_in[0];
    const float* c0v = (const float*)d_in[1];
    const float* c0g = (const float*)d_in[2];
    const float* c1v = (const float*)d_in[3];
    const float* c1g = (const float*)d_in[4];
    const float* c2v = (const float*)d_in[5];
    const float* c2g = (const float*)d_in[6];
    const float* c3v = (const float*)d_in[7];
    const float* c3g = (const float*)d_in[8];
    const float* lv  = (const float*)d_in[9];
    const float* lg  = (const float*)d_in[10];

    float *bufA, *bufB, *w0, *w1, *w2, *w3, *wl;
    cudaGetSymbolAddress((void**)&bufA, g_bufA);
    cudaGetSymbolAddress((void**)&bufB, g_bufB);
    cudaGetSymbolAddress((void**)&w0, g_w0);
    cudaGetSymbolAddress((void**)&w1, g_w1);
    cudaGetSymbolAddress((void**)&w2, g_w2);
    cudaGetSymbolAddress((void**)&w3, g_w3);
    cudaGetSymbolAddress((void**)&wl, g_wl);

    const int B = 32, T = 50, BT = B * T;

    // (1) weight norms
    wnorm_all<<<131, 64>>>(c0v, c0g, c1v, c1g, c2v, c2g, c3v, c3g, lv, lg,
                           w0, w1, w2, w3, wl);

    const int smem2 = (2 * 16 * 18 * 18 + 9 * 16 * 32) * 4;    // 59904
    const int smem3 = (4 * 32 * 10 * 10 + 9 * 32 * 32) * 4;    // 88064 (IPB=4, COG=2)

    cudaFuncSetAttribute((const void*)conv2_allcg,
                         cudaFuncAttributeMaxDynamicSharedMemorySize, smem2);
    cudaFuncSetAttribute((const void*)conv3x3_blk<32, 64, 8, 4, 2, 2>,
                         cudaFuncAttributeMaxDynamicSharedMemorySize, smem3);

    // (2) layer 0 fused (v3)
    l0_fused<<<B * 8, 512>>>(x, w0, bufB);
    // (3) layer 1 conv (all-cg, R15 proven)
    conv1_allcg<<<BT, 256>>>(bufB, w1, bufA);
    // (4) iaf1 — profiled slot
    {
        int total = B * 16 * 16 * 8;
        iaf_pool_kernel<16, 32, 50><<<(total + 255) / 256, 256>>>(bufA, bufB, B);
    }
    // layer 2: new all-cg kernel (2 images/block)
    conv2_allcg<<<BT / 2, 256, smem2>>>(bufB, w2, bufA);
    {
        int total = B * 32 * 8 * 4;
        iaf_pool_kernel<32, 16, 50><<<(total + 255) / 256, 256>>>(bufA, bufB, B);
    }
    // layer 3: IPB=4, COG=2 -> full thread utilization (ITEMS=256)
    conv3x3_blk<32, 64, 8, 4, 2, 2><<<(BT / 4) * 2, 256, smem3>>>(bufB, w3, bufA);
    {
        int total = B * 64 * 4 * 2;
        iaf_pool_kernel<64, 8, 50><<<(total + 255) / 256, 256>>>(bufA, bufB, B);
    }
    // linear
    linear_kernel<<<BT, 32>>>(bufB, wl, (float*)d_out);
}

// round 17
// speedup vs baseline: 1.1409x; 1.0438x over previous
#include <cuda_runtime.h>
#include <math.h>

#define THRESH 0.1f

typedef unsigned long long u64;

__device__ __forceinline__ u64 pack2(float lo, float hi) {
    u64 r;
    asm("mov.b64 %0, {%1, %2};" : "=l"(r) : "f"(lo), "f"(hi));
    return r;
}
__device__ __forceinline__ void unpack2(u64 v, float& lo, float& hi) {
    asm("mov.b64 {%0, %1}, %2;" : "=f"(lo), "=f"(hi) : "l"(v));
}
__device__ __forceinline__ u64 fma2(u64 a, u64 b, u64 c) {
    u64 d;
    asm("fma.rn.f32x2 %0, %1, %2, %3;" : "=l"(d) : "l"(a), "l"(b), "l"(c));
    return d;
}

// ---------------- scratch (no allocations allowed) ----------------
__device__ float g_bufA[26214400];
__device__ float g_bufB[13107200];
__device__ float g_w0[9 * 2 * 8];    // [k][ci][co]
__device__ float g_w1[9 * 8 * 16];
__device__ float g_w2[9 * 16 * 32];
__device__ float g_w3[9 * 32 * 64];
__device__ float g_wl[11 * 1024];

__global__ void noop_kernel() {}

// ---------------- weight norm v2: smem-staged rows, serial chain from smem ----------------
// The reduction chain order is IDENTICAL to before (sequential i=0..N-1), but
// values are staged into smem by 256 threads first, so thread0's serial chain
// hits LDS (pipelined) instead of serial DRAM latency. Bit-exact.
__global__ void __launch_bounds__(256) wnorm_all(
        const float* __restrict__ c0v, const float* __restrict__ c0g,
        const float* __restrict__ c1v, const float* __restrict__ c1g,
        const float* __restrict__ c2v, const float* __restrict__ c2g,
        const float* __restrict__ c3v, const float* __restrict__ c3g,
        const float* __restrict__ lv,  const float* __restrict__ lg,
        float* __restrict__ w0, float* __restrict__ w1,
        float* __restrict__ w2, float* __restrict__ w3,
        float* __restrict__ wl) {
    __shared__ float buf[1024];
    __shared__ float snorm;

    int r = blockIdx.x;
    const float* v = 0; const float* g = 0; float* w = 0;
    int CIN = 0, COUT = 0, co = 0;
    bool lin = false;
    if (r < 8)        { v = c0v; g = c0g; w = w0; CIN = 2;  COUT = 8;  co = r; }
    else if (r < 24)  { v = c1v; g = c1g; w = w1; CIN = 8;  COUT = 16; co = r - 8; }
    else if (r < 56)  { v = c2v; g = c2g; w = w2; CIN = 16; COUT = 32; co = r - 24; }
    else if (r < 120) { v = c3v; g = c3g; w = w3; CIN = 32; COUT = 64; co = r - 56; }
    else              { lin = true; co = r - 120; }

    if (!lin) {
        const int N = CIN * 9;
        const float* vr = v + (size_t)co * N;
        for (int i = threadIdx.x; i < N; i += 256) buf[i] = vr[i];
        __syncthreads();
        if (threadIdx.x == 0) {
            float s = 0.f;
            for (int i = 0; i < N; i++) s = __fadd_rn(s, __fmul_rn(buf[i], buf[i]));
            snorm = sqrtf(s);
        }
        __syncthreads();
        float norm = snorm, gg = g[co];
        for (int idx = threadIdx.x; idx < N; idx += 256) {
            int ci = idx / 9, k = idx % 9;
            w[((size_t)k * CIN + ci) * COUT + co] = __fdiv_rn(__fmul_rn(gg, buf[idx]), norm);
        }
    } else {
        const float* vr = lv + (size_t)co * 1024;
        for (int i = threadIdx.x; i < 1024; i += 256) buf[i] = vr[i];
        __syncthreads();
        if (threadIdx.x == 0) {
            float s = 0.f;
            for (int i = 0; i < 1024; i++) s = __fadd_rn(s, __fmul_rn(buf[i], buf[i]));
            snorm = sqrtf(s);
        }
        __syncthreads();
        float norm = snorm, gg = lg[co];
        for (int i = threadIdx.x; i < 1024; i += 256)
            wl[(size_t)co * 1024 + i] = __fdiv_rn(__fmul_rn(gg, buf[i]), norm);
    }
}

// ---------------- layer 0 fully fused (v3 — proven) ----------------
__global__ void __launch_bounds__(512) l0_fused(const float* __restrict__ x,
                                                const float* __restrict__ wt,
                                                float* __restrict__ out) {
    const int PW = 36, CPH = 18 * 36, BUFSZ = 2 * 18 * 36;
    __shared__ float sw[144];
    __shared__ float sin[2][BUFSZ];

    const int b = blockIdx.x >> 3;
    const int tile = blockIdx.x & 7;
    const int ty0 = (tile >> 1) * 16;
    const int tx0 = (tile & 1) * 32;
    const int tid = threadIdx.x;
    if (tid < 144) sw[tid] = wt[tid];

    const int cg = tid >> 7;
    const int ptid = tid & 127;
    const int py = ptid >> 4, px = ptid & 15;
    const int y0 = 2 * py, x0 = 2 * px;
    const int co0 = cg * 2;

    int srcOff[3], dstOff[3];
    bool ldOk[3], ldAct[3];
#pragma unroll
    for (int j = 0; j < 3; j++) {
        int i = tid + j * 512;
        bool act = i < 1224;
        int ii = act ? i : 0;
        int c = ii / 612;
        int r = ii - c * 612;
        int yy = r / 34, xx = r - yy * 34;
        int gy = ty0 + yy - 1, gx = tx0 + xx - 1;
        ldAct[j] = act;
        ldOk[j] = act && gy >= 0 && gy < 64 && gx >= 0 && gx < 64;
        srcOff[j] = c * 4096 + gy * 64 + gx;
        dstOff[j] = c * CPH + yy * PW + xx;
    }

    {
        const float* xp = x + ((size_t)(b * 50)) * 2 * 4096;
#pragma unroll
        for (int j = 0; j < 3; j++) {
            if (ldAct[j]) {
                float v = ldOk[j] ? xp[srcOff[j]] : 0.f;
                sin[0][dstOff[j]] = v;
            }
        }
    }

    float m[2][4];
#pragma unroll
    for (int c = 0; c < 2; c++) { m[c][0] = 0.f; m[c][1] = 0.f; m[c][2] = 0.f; m[c][3] = 0.f; }

    const int Y2 = (ty0 >> 1) + py, X2 = (tx0 >> 1) + px;

    int p = 0;
    for (int t = 0; t < 50; t++) {
        __syncthreads();

        const float* sbuf = sin[p];
        float inr[2][4][4];
#pragma unroll
        for (int ci = 0; ci < 2; ci++) {
#pragma unroll
            for (int r = 0; r < 4; r++) {
                const float* rp = sbuf + ci * CPH + (y0 + r) * PW + x0;
                float2 a = *reinterpret_cast<const float2*>(rp);
                float2 bb = *reinterpret_cast<const float2*>(rp + 2);
                inr[ci][r][0] = a.x; inr[ci][r][1] = a.y;
                inr[ci][r][2] = bb.x; inr[ci][r][3] = bb.y;
            }
        }

        if (t < 49) {
            const float* xp = x + ((size_t)(b * 50 + t + 1)) * 2 * 4096;
            float* dbuf = sin[p ^ 1];
#pragma unroll
            for (int j = 0; j < 3; j++) {
                if (ldAct[j]) {
                    float v = ldOk[j] ? xp[srcOff[j]] : 0.f;
                    dbuf[dstOff[j]] = v;
                }
            }
        }

        float acc[2][4];
#pragma unroll
        for (int c = 0; c < 2; c++) { acc[c][0] = 0.f; acc[c][1] = 0.f; acc[c][2] = 0.f; acc[c][3] = 0.f; }
#pragma unroll
        for (int ky = 0; ky < 3; ky++) {
#pragma unroll
            for (int kx = 0; kx < 3; kx++) {
#pragma unroll
                for (int ci = 0; ci < 2; ci++) {
                    float i00 = inr[ci][ky][kx];
                    float i01 = inr[ci][ky][kx + 1];
                    float i10 = inr[ci][ky + 1][kx];
                    float i11 = inr[ci][ky + 1][kx + 1];
                    const float2 wv = *reinterpret_cast<const float2*>(
                        sw + ((ky * 3 + kx) * 2 + ci) * 8 + co0);
                    acc[0][0] = __fmaf_rn(i00, wv.x, acc[0][0]);
                    acc[0][1] = __fmaf_rn(i01, wv.x, acc[0][1]);
                    acc[0][2] = __fmaf_rn(i10, wv.x, acc[0][2]);
                    acc[0][3] = __fmaf_rn(i11, wv.x, acc[0][3]);
                    acc[1][0] = __fmaf_rn(i00, wv.y, acc[1][0]);
                    acc[1][1] = __fmaf_rn(i01, wv.y, acc[1][1]);
                    acc[1][2] = __fmaf_rn(i10, wv.y, acc[1][2]);
                    acc[1][3] = __fmaf_rn(i11, wv.y, acc[1][3]);
                }
            }
        }

        float* op = out + ((size_t)(b * 50 + t) * 8 + co0) * 1024 + Y2 * 32 + X2;
#pragma unroll
        for (int c = 0; c < 2; c++) {
            float s = 0.f;
            m[c][0] = __fadd_rn(m[c][0], acc[c][0]);
            m[c][1] = __fadd_rn(m[c][1], acc[c][1]);
            m[c][2] = __fadd_rn(m[c][2], acc[c][2]);
            m[c][3] = __fadd_rn(m[c][3], acc[c][3]);
            if (m[c][0] >= THRESH) { m[c][0] = __fadd_rn(m[c][0], -THRESH); s += 0.25f; }
            if (m[c][1] >= THRESH) { m[c][1] = __fadd_rn(m[c][1], -THRESH); s += 0.25f; }
            if (m[c][2] >= THRESH) { m[c][2] = __fadd_rn(m[c][2], -THRESH); s += 0.25f; }
            if (m[c][3] >= THRESH) { m[c][3] = __fadd_rn(m[c][3], -THRESH); s += 0.25f; }
            op[c * 1024] = s;
        }
        p ^= 1;
    }
}

// ---------------- conv1 all-couts: 8->16, 32x32 (R15 proven) ----------------
__global__ void __launch_bounds__(256, 2)
conv1_allcg(const float* __restrict__ in, const float* __restrict__ wt,
            float* __restrict__ out) {
    const int W = 32, HW = 1024, PW = 34, PHW = 34 * 34, CIN = 8, COUT = 16;
    __shared__ float smem[CIN * PHW + 9 * CIN * COUT];
    float* sin = smem;
    float* sw = smem + CIN * PHW;

    const int n = blockIdx.x;
    for (int i = threadIdx.x; i < CIN * PHW; i += 256) sin[i] = 0.f;
    for (int i = threadIdx.x; i < 9 * CIN * COUT; i += 256) sw[i] = wt[i];
    __syncthreads();
    for (int i = threadIdx.x; i < CIN * HW; i += 256) {
        int ci = i >> 10;
        int p = i & 1023;
        int y = p >> 5, x = p & 31;
        sin[ci * PHW + (y + 1) * PW + (x + 1)] = in[(size_t)n * CIN * HW + i];
    }
    __syncthreads();

    const int q = threadIdx.x;
    const int y2 = q >> 4, x2 = q & 15;
    const int y0 = 2 * y2, x0 = 2 * x2;

    u64 acc[8][4];
#pragma unroll
    for (int cp = 0; cp < 8; cp++) {
        acc[cp][0] = 0ULL; acc[cp][1] = 0ULL; acc[cp][2] = 0ULL; acc[cp][3] = 0ULL;
    }

#pragma unroll
    for (int ky = 0; ky < 3; ky++) {
#pragma unroll
        for (int kx = 0; kx < 3; kx++) {
            const float* ip = sin + (y0 + ky) * PW + (x0 + kx);
            const float* wpb = sw + (ky * 3 + kx) * CIN * COUT;
#pragma unroll 2
            for (int ci = 0; ci < CIN; ci++) {
                float i00, i01, i10, i11;
                if (kx != 1) {
                    float2 a = *reinterpret_cast<const float2*>(ip + ci * PHW);
                    float2 bb = *reinterpret_cast<const float2*>(ip + ci * PHW + PW);
                    i00 = a.x; i01 = a.y; i10 = bb.x; i11 = bb.y;
                } else {
                    i00 = ip[ci * PHW];
                    i01 = ip[ci * PHW + 1];
                    i10 = ip[ci * PHW + PW];
                    i11 = ip[ci * PHW + PW + 1];
                }
                u64 p00 = pack2(i00, i00);
                u64 p01 = pack2(i01, i01);
                u64 p10 = pack2(i10, i10);
                u64 p11 = pack2(i11, i11);
                const ulonglong2* wq = reinterpret_cast<const ulonglong2*>(wpb + ci * COUT);
                ulonglong2 wA = wq[0];
                ulonglong2 wB = wq[1];
                ulonglong2 wC = wq[2];
                ulonglong2 wD = wq[3];
                u64 ws[8] = {wA.x, wA.y, wB.x, wB.y, wC.x, wC.y, wD.x, wD.y};
#pragma unroll
                for (int cp = 0; cp < 8; cp++) {
                    acc[cp][0] = fma2(p00, ws[cp], acc[cp][0]);
                    acc[cp][1] = fma2(p01, ws[cp], acc[cp][1]);
                    acc[cp][2] = fma2(p10, ws[cp], acc[cp][2]);
                    acc[cp][3] = fma2(p11, ws[cp], acc[cp][3]);
                }
            }
        }
    }

    float* op = out + ((size_t)n * COUT) * HW + y0 * W + x0;
#pragma unroll
    for (int cp = 0; cp < 8; cp++) {
        float lo0, hi0, lo1, hi1, lo2, hi2, lo3, hi3;
        unpack2(acc[cp][0], lo0, hi0);
        unpack2(acc[cp][1], lo1, hi1);
        unpack2(acc[cp][2], lo2, hi2);
        unpack2(acc[cp][3], lo3, hi3);
        float* opc = op + (2 * cp) * HW;
        float2 r0; r0.x = lo0; r0.y = lo1;
        float2 r1; r1.x = lo2; r1.y = lo3;
        *reinterpret_cast<float2*>(opc) = r0;
        *reinterpret_cast<float2*>(opc + W) = r1;
        float* opc2 = op + (2 * cp + 1) * HW;
        float2 s0; s0.x = hi0; s0.y = hi1;
        float2 s1; s1.x = hi2; s1.y = hi3;
        *reinterpret_cast<float2*>(opc2) = s0;
        *reinterpret_cast<float2*>(opc2 + W) = s1;
    }
}

// ---------------- conv2: 16->32, 16x16, 16 couts/thread, 2 images/block ----------------
__global__ void __launch_bounds__(256, 2)
conv2_allcg(const float* __restrict__ in, const float* __restrict__ wt,
            float* __restrict__ out) {
    const int W = 16, HW = 256, PW = 18, PHW = 18 * 18, CIN = 16, COUT = 32;
    extern __shared__ float smem[];
    float* sin = smem;
    float* sw = smem + 2 * CIN * PHW;

    const int n0 = blockIdx.x * 2;
    for (int i = threadIdx.x; i < 2 * CIN * PHW; i += 256) sin[i] = 0.f;
    for (int i = threadIdx.x; i < 9 * CIN * COUT; i += 256) sw[i] = wt[i];
    __syncthreads();
    for (int i = threadIdx.x; i < 2 * CIN * HW; i += 256) {
        int img = i >> 12;
        int rem = i & 4095;
        int ci = rem >> 8;
        int p = rem & 255;
        int y = p >> 4, x = p & 15;
        sin[img * CIN * PHW + ci * PHW + (y + 1) * PW + (x + 1)] = in[(size_t)n0 * CIN * HW + i];
    }
    __syncthreads();

    const int cg = threadIdx.x >> 7;
    const int img = (threadIdx.x >> 6) & 1;
    const int q = threadIdx.x & 63;
    const int y2 = q >> 3, x2 = q & 7;
    const int y0 = 2 * y2, x0 = 2 * x2;
    const float* simg = sin + img * CIN * PHW;

    u64 acc[8][4];
#pragma unroll
    for (int cp = 0; cp < 8; cp++) {
        acc[cp][0] = 0ULL; acc[cp][1] = 0ULL; acc[cp][2] = 0ULL; acc[cp][3] = 0ULL;
    }

#pragma unroll
    for (int ky = 0; ky < 3; ky++) {
#pragma unroll
        for (int kx = 0; kx < 3; kx++) {
            const float* ip = simg + (y0 + ky) * PW + (x0 + kx);
            const float* wpb = sw + (ky * 3 + kx) * CIN * COUT + cg * 16;
#pragma unroll 4
            for (int ci = 0; ci < CIN; ci++) {
                float i00, i01, i10, i11;
                if (kx != 1) {
                    float2 a = *reinterpret_cast<const float2*>(ip + ci * PHW);
                    float2 bb = *reinterpret_cast<const float2*>(ip + ci * PHW + PW);
                    i00 = a.x; i01 = a.y; i10 = bb.x; i11 = bb.y;
                } else {
                    i00 = ip[ci * PHW];
                    i01 = ip[ci * PHW + 1];
                    i10 = ip[ci * PHW + PW];
                    i11 = ip[ci * PHW + PW + 1];
                }
                u64 p00 = pack2(i00, i00);
                u64 p01 = pack2(i01, i01);
                u64 p10 = pack2(i10, i10);
                u64 p11 = pack2(i11, i11);
                const ulonglong2* wq = reinterpret_cast<const ulonglong2*>(wpb + ci * COUT);
                ulonglong2 wA = wq[0];
                ulonglong2 wB = wq[1];
                ulonglong2 wC = wq[2];
                ulonglong2 wD = wq[3];
                u64 ws[8] = {wA.x, wA.y, wB.x, wB.y, wC.x, wC.y, wD.x, wD.y};
#pragma unroll
                for (int cp = 0; cp < 8; cp++) {
                    acc[cp][0] = fma2(p00, ws[cp], acc[cp][0]);
                    acc[cp][1] = fma2(p01, ws[cp], acc[cp][1]);
                    acc[cp][2] = fma2(p10, ws[cp], acc[cp][2]);
                    acc[cp][3] = fma2(p11, ws[cp], acc[cp][3]);
                }
            }
        }
    }

    float* op = out + ((size_t)(n0 + img) * COUT + cg * 16) * HW + y0 * W + x0;
#pragma unroll
    for (int cp = 0; cp < 8; cp++) {
        float lo0, hi0, lo1, hi1, lo2, hi2, lo3, hi3;
        unpack2(acc[cp][0], lo0, hi0);
        unpack2(acc[cp][1], lo1, hi1);
        unpack2(acc[cp][2], lo2, hi2);
        unpack2(acc[cp][3], lo3, hi3);
        float* opc = op + (2 * cp) * HW;
        float2 r0; r0.x = lo0; r0.y = lo1;
        float2 r1; r1.x = lo2; r1.y = lo3;
        *reinterpret_cast<float2*>(opc) = r0;
        *reinterpret_cast<float2*>(opc + W) = r1;
        float* opc2 = op + (2 * cp + 1) * HW;
        float2 s0; s0.x = hi0; s0.y = hi1;
        float2 s1; s1.x = hi2; s1.y = hi3;
        *reinterpret_cast<float2*>(opc2) = s0;
        *reinterpret_cast<float2*>(opc2 + W) = s1;
    }
}

// ---------------- generic conv (conv3), packed f32x2 ----------------
template <int CIN, int COUT, int H, int IPB, int COG, int MINB>
__global__ void __launch_bounds__(256, MINB)
conv3x3_blk(const float* __restrict__ in, const float* __restrict__ wt,
            float* __restrict__ out) {
    const int W = H, HW = H * W, PW = W + 2, PHW = (H + 2) * PW;
    const int HW4 = HW / 4, W2 = W / 2;
    const int CPB = COUT / COG, NCG = CPB / 8;
    extern __shared__ float smem[];
    float* sin = smem;
    float* sw = smem + IPB * CIN * PHW;

    const int ngrp = blockIdx.x / COG;
    const int cog = blockIdx.x - ngrp * COG;
    const int coB = cog * CPB;
    const int n0 = ngrp * IPB;

    for (int i = threadIdx.x; i < IPB * CIN * PHW; i += blockDim.x) sin[i] = 0.f;
    if (COG == 1) {
        for (int i = threadIdx.x; i < 9 * CIN * CPB; i += blockDim.x) sw[i] = wt[i];
    } else {
        for (int i = threadIdx.x; i < 9 * CIN * CPB; i += blockDim.x) {
            int kci = i / CPB, c = i - kci * CPB;
            sw[i] = wt[kci * COUT + coB + c];
        }
    }
    __syncthreads();
    for (int i = threadIdx.x; i < IPB * CIN * HW; i += blockDim.x) {
        int img = i / (CIN * HW);
        int rem = i - img * (CIN * HW);
        int ci = rem / HW;
        int p = rem - ci * HW;
        int y = p / W;
        int x = p - y * W;
        sin[img * CIN * PHW + ci * PHW + (y + 1) * PW + (x + 1)] = in[(size_t)n0 * CIN * HW + i];
    }
    __syncthreads();

    const int ITEMS = IPB * HW4 * NCG;
    for (int item = threadIdx.x; item < ITEMS; item += blockDim.x) {
        int cg = item / (IPB * HW4);
        int rem = item - cg * (IPB * HW4);
        int img = rem / HW4;
        int q = rem - img * HW4;
        int y2 = q / W2, x2 = q - y2 * W2;
        int y0 = 2 * y2, x0 = 2 * x2;
        const float* simg = sin + img * CIN * PHW;

        u64 accP[4][4];
#pragma unroll
        for (int cp = 0; cp < 4; cp++) {
            accP[cp][0] = 0ULL; accP[cp][1] = 0ULL; accP[cp][2] = 0ULL; accP[cp][3] = 0ULL;
        }
#pragma unroll
        for (int ky = 0; ky < 3; ky++) {
#pragma unroll
            for (int kx = 0; kx < 3; kx++) {
                const float* ip = simg + (y0 + ky) * PW + (x0 + kx);
                const float* wp = sw + (ky * 3 + kx) * CIN * CPB + cg * 8;
#pragma unroll 4
                for (int ci = 0; ci < CIN; ci++) {
                    float i00, i01, i10, i11;
                    if (kx != 1) {
                        float2 a = *reinterpret_cast<const float2*>(ip + ci * PHW);
                        float2 bb = *reinterpret_cast<const float2*>(ip + ci * PHW + PW);
                        i00 = a.x; i01 = a.y; i10 = bb.x; i11 = bb.y;
                    } else {
                        i00 = ip[ci * PHW];
                        i01 = ip[ci * PHW + 1];
                        i10 = ip[ci * PHW + PW];
                        i11 = ip[ci * PHW + PW + 1];
                    }
                    u64 p00 = pack2(i00, i00);
                    u64 p01 = pack2(i01, i01);
                    u64 p10 = pack2(i10, i10);
                    u64 p11 = pack2(i11, i11);
                    const ulonglong2* wq2 = reinterpret_cast<const ulonglong2*>(wp + ci * CPB);
                    ulonglong2 wA = wq2[0];
                    ulonglong2 wB = wq2[1];
                    accP[0][0] = fma2(p00, wA.x, accP[0][0]);
                    accP[0][1] = fma2(p01, wA.x, accP[0][1]);
                    accP[0][2] = fma2(p10, wA.x, accP[0][2]);
                    accP[0][3] = fma2(p11, wA.x, accP[0][3]);
                    accP[1][0] = fma2(p00, wA.y, accP[1][0]);
                    accP[1][1] = fma2(p01, wA.y, accP[1][1]);
                    accP[1][2] = fma2(p10, wA.y, accP[1][2]);
                    accP[1][3] = fma2(p11, wA.y, accP[1][3]);
                    accP[2][0] = fma2(p00, wB.x, accP[2][0]);
                    accP[2][1] = fma2(p01, wB.x, accP[2][1]);
                    accP[2][2] = fma2(p10, wB.x, accP[2][2]);
                    accP[2][3] = fma2(p11, wB.x, accP[2][3]);
                    accP[3][0] = fma2(p00, wB.y, accP[3][0]);
                    accP[3][1] = fma2(p01, wB.y, accP[3][1]);
                    accP[3][2] = fma2(p10, wB.y, accP[3][2]);
                    accP[3][3] = fma2(p11, wB.y, accP[3][3]);
                }
            }
        }
        float* op = out + ((size_t)(n0 + img) * COUT + coB + cg * 8) * HW + y0 * W + x0;
#pragma unroll
        for (int cp = 0; cp < 4; cp++) {
            float lo0, hi0, lo1, hi1, lo2, hi2, lo3, hi3;
            unpack2(accP[cp][0], lo0, hi0);
            unpack2(accP[cp][1], lo1, hi1);
            unpack2(accP[cp][2], lo2, hi2);
            unpack2(accP[cp][3], lo3, hi3);
            float* opc = op + (2 * cp) * HW;
            float2 r0; r0.x = lo0; r0.y = lo1;
            float2 r1; r1.x = lo2; r1.y = lo3;
            *reinterpret_cast<float2*>(opc) = r0;
            *reinterpret_cast<float2*>(opc + W) = r1;
            float* opc2 = op + (2 * cp + 1) * HW;
            float2 s0; s0.x = hi0; s0.y = hi1;
            float2 s1; s1.x = hi2; s1.y = hi3;
            *reinterpret_cast<float2*>(opc2) = s0;
            *reinterpret_cast<float2*>(opc2 + W) = s1;
        }
    }
}

// ---------------- fused IAF + 2x2 avg pool: 2 pooled pixels / thread ----------------
template <int C, int H, int T>
__global__ void iaf_pool_kernel(const float* __restrict__ syn, float* __restrict__ out, int B) {
    const int W = H, HW = H * W, H2 = H / 2, W2 = W / 2, HW2 = H2 * W2, WP = W2 / 2;
    int idx = blockIdx.x * blockDim.x + threadIdx.x;
    int total = B * C * H2 * WP;
    if (idx >= total) return;
    int xp = idx % WP;
    int r = idx / WP;
    int y2 = r % H2;
    r /= H2;
    int c = r % C;
    int b = r / C;

    const size_t stride = (size_t)C * HW;
    const size_t ostride = (size_t)C * HW2;
    const float* p = syn + ((size_t)b * T) * stride + (size_t)c * HW + (size_t)(2 * y2) * W + 4 * xp;
    float* q = out + ((size_t)b * T) * ostride + (size_t)c * HW2 + (size_t)y2 * W2 + 2 * xp;

    float v0 = 0.f, v1 = 0.f, v2 = 0.f, v3 = 0.f;
    float u0 = 0.f, u1 = 0.f, u2 = 0.f, u3 = 0.f;
#pragma unroll 2
    for (int t = 0; t < T; t++) {
        const float4 a = *reinterpret_cast<const float4*>(p);
        const float4 bb = *reinterpret_cast<const float4*>(p + W);
        v0 = __fadd_rn(v0, a.x);
        v1 = __fadd_rn(v1, a.y);
        v2 = __fadd_rn(v2, bb.x);
        v3 = __fadd_rn(v3, bb.y);
        u0 = __fadd_rn(u0, a.z);
        u1 = __fadd_rn(u1, a.w);
        u2 = __fadd_rn(u2, bb.z);
        u3 = __fadd_rn(u3, bb.w);
        float s = 0.f, s2 = 0.f;
        if (v0 >= THRESH) { v0 = __fadd_rn(v0, -THRESH); s += 0.25f; }
        if (v1 >= THRESH) { v1 = __fadd_rn(v1, -THRESH); s += 0.25f; }
        if (v2 >= THRESH) { v2 = __fadd_rn(v2, -THRESH); s += 0.25f; }
        if (v3 >= THRESH) { v3 = __fadd_rn(v3, -THRESH); s += 0.25f; }
        if (u0 >= THRESH) { u0 = __fadd_rn(u0, -THRESH); s2 += 0.25f; }
        if (u1 >= THRESH) { u1 = __fadd_rn(u1, -THRESH); s2 += 0.25f; }
        if (u2 >= THRESH) { u2 = __fadd_rn(u2, -THRESH); s2 += 0.25f; }
        if (u3 >= THRESH) { u3 = __fadd_rn(u3, -THRESH); s2 += 0.25f; }
        float2 sv; sv.x = s; sv.y = s2;
        *reinterpret_cast<float2*>(q) = sv;
        p += stride;
        q += ostride;
    }
}

// ---------------- final linear: (BT,1024) @ (11,1024)^T ----------------
__global__ void linear_kernel(const float* __restrict__ in, const float* __restrict__ w,
                              float* __restrict__ out) {
    int n = blockIdx.x;
    __shared__ float srow[1024];
    for (int i = threadIdx.x; i < 1024; i += blockDim.x) srow[i] = in[(size_t)n * 1024 + i];
    __syncthreads();
    int cls = threadIdx.x;
    if (cls >= 11) return;
    const float* wr = w + (size_t)cls * 1024;
    float acc = 0.f;
    for (int i = 0; i < 1024; i++) acc = __fmaf_rn(srow[i], wr[i], acc);
    out[(size_t)n * 11 + cls] = acc;
}

extern "C" void kernel_launch(void* const* d_in, const int* in_sizes, int n_in,
                              void* d_out, int out_size) {
    const float* x   = (const float*)d_in[0];
    const float* c0v = (const float*)d_in[1];
    const float* c0g = (const float*)d_in[2];
    const float* c1v = (const float*)d_in[3];
    const float* c1g = (const float*)d_in[4];
    const float* c2v = (const float*)d_in[5];
    const float* c2g = (const float*)d_in[6];
    const float* c3v = (const float*)d_in[7];
    const float* c3g = (const float*)d_in[8];
    const float* lv  = (const float*)d_in[9];
    const float* lg  = (const float*)d_in[10];

    float *bufA, *bufB, *w0, *w1, *w2, *w3, *wl;
    cudaGetSymbolAddress((void**)&bufA, g_bufA);
    cudaGetSymbolAddress((void**)&bufB, g_bufB);
    cudaGetSymbolAddress((void**)&w0, g_w0);
    cudaGetSymbolAddress((void**)&w1, g_w1);
    cudaGetSymbolAddress((void**)&w2, g_w2);
    cudaGetSymbolAddress((void**)&w3, g_w3);
    cudaGetSymbolAddress((void**)&wl, g_wl);

    const int B = 32, T = 50, BT = B * T;

    // (1) weight norms — v2 (smem-staged serial chains, bit-exact)
    wnorm_all<<<131, 256>>>(c0v, c0g, c1v, c1g, c2v, c2g, c3v, c3g, lv, lg,
                            w0, w1, w2, w3, wl);

    const int smem2 = (2 * 16 * 18 * 18 + 9 * 16 * 32) * 4;    // 59904
    const int smem3 = (4 * 32 * 10 * 10 + 9 * 32 * 32) * 4;    // 88064 (IPB=4, COG=2)

    cudaFuncSetAttribute((const void*)conv2_allcg,
                         cudaFuncAttributeMaxDynamicSharedMemorySize, smem2);
    cudaFuncSetAttribute((const void*)conv3x3_blk<32, 64, 8, 4, 2, 2>,
                         cudaFuncAttributeMaxDynamicSharedMemorySize, smem3);

    // (2) layer 0 fused (v3)
    l0_fused<<<B * 8, 512>>>(x, w0, bufB);
    // (3) layer 1 conv
    conv1_allcg<<<BT, 256>>>(bufB, w1, bufA);
    // (4) iaf1
    {
        int total = B * 16 * 16 * 8;
        iaf_pool_kernel<16, 32, 50><<<(total + 255) / 256, 256>>>(bufA, bufB, B);
    }
    // layer 2
    conv2_allcg<<<BT / 2, 256, smem2>>>(bufB, w2, bufA);
    {
        int total = B * 32 * 8 * 4;
        iaf_pool_kernel<32, 16, 50><<<(total + 255) / 256, 256>>>(bufA, bufB, B);
    }
    // layer 3
    conv3x3_blk<32, 64, 8, 4, 2, 2><<<(BT / 4) * 2, 256, smem3>>>(bufB, w3, bufA);
    {
        int total = B * 64 * 4 * 2;
        iaf_pool_kernel<64, 8, 50><<<(total + 255) / 256, 256>>>(bufA, bufB, B);
    }
    // linear
    linear_kernel<<<BT, 32>>>(bufB, wl, (float*)d_out);
}